// round 1
// baseline (speedup 1.0000x reference)
#include <cuda_runtime.h>
#include <math.h>

#define BSZ 8192
#define SLN 49
#define FDIM 11
#define DEC_IN 138

// ---------------- device scratch (static; no allocations allowed) ----------------
__device__ float g_sum[9];
__device__ float g_sumsq[9];
__device__ float g_mean[9];
__device__ float g_rstd[9];
__device__ float g_enc[BSZ * DEC_IN];
__device__ float g_h0[BSZ * 512];
__device__ float g_h1[BSZ * 256];

// ---------------- batch-norm statistics ----------------
__global__ void bn_zero_kernel() {
    if (threadIdx.x < 9) { g_sum[threadIdx.x] = 0.f; g_sumsq[threadIdx.x] = 0.f; }
}

__global__ void bn_acc_kernel(const float* __restrict__ in) {
    float ls[9], lq[9];
#pragma unroll
    for (int f = 0; f < 9; f++) { ls[f] = 0.f; lq[f] = 0.f; }
    int idx0 = blockIdx.x * blockDim.x + threadIdx.x;
    for (int r = idx0; r < BSZ * SLN; r += gridDim.x * blockDim.x) {
        const float* p = in + (size_t)r * FDIM;
#pragma unroll
        for (int f = 0; f < 9; f++) {
            float v = p[f < 8 ? f : 10];
            ls[f] += v; lq[f] += v * v;
        }
    }
#pragma unroll
    for (int f = 0; f < 9; f++) {
#pragma unroll
        for (int o = 16; o; o >>= 1) {
            ls[f] += __shfl_down_sync(0xffffffffu, ls[f], o);
            lq[f] += __shfl_down_sync(0xffffffffu, lq[f], o);
        }
    }
    if ((threadIdx.x & 31) == 0) {
#pragma unroll
        for (int f = 0; f < 9; f++) {
            atomicAdd(&g_sum[f], ls[f]);
            atomicAdd(&g_sumsq[f], lq[f]);
        }
    }
}

__global__ void bn_fin_kernel() {
    int f = threadIdx.x;
    if (f < 9) {
        float n = (float)(BSZ * SLN);
        float mu = g_sum[f] / n;
        float var = g_sumsq[f] / n - mu * mu;
        g_mean[f] = mu;
        g_rstd[f] = rsqrtf(var + 1e-5f);
    }
}

// ---------------- main per-element transformer kernel ----------------
struct MainParams {
    const float *in, *dists, *gamma, *beta;
    const float *xe_w1, *xe_b1, *xe_w2, *xe_b2;
    const float *ye_w1, *ye_b1, *ye_w2, *ye_b2;
    const float *learnable_y, *hidden_tokens;
    const float *Wq, *Wk, *Wv, *Wo, *Wq2, *Wk2, *Wv2, *Wo2;
};

struct __align__(16) Smem {
    float in[SLN][12];      // normalized input (11 used)
    float cs[SLN][4];
    float sn[SLN][4];
    float bias[48];
    float xe[SLN][64];
    float ye[SLN][64];
    float K[48][64];
    float V[48][64];
    float H[4][64];
    union {
        float tmp[SLN][64];
        struct {
            float sc[32][48];   // [h*4+i][t]
            float q[4][64];
            float o[4][64];
            float k2[4][64];
            float v2[4][64];
            float qc[64];
            float outv[64];
            float a2[32];
        } a;
    } u;
};

__device__ __forceinline__ float dot64(const float* __restrict__ arow, const float* __restrict__ w) {
    const float4* a4 = reinterpret_cast<const float4*>(arow);
    float acc = 0.f;
#pragma unroll
    for (int k = 0; k < 16; k++) {
        float4 c = a4[k];
        acc += c.x * w[4 * k] + c.y * w[4 * k + 1] + c.z * w[4 * k + 2] + c.w * w[4 * k + 3];
    }
    return acc;
}

__global__ void __launch_bounds__(256) k_main(MainParams P, float* __restrict__ enc) {
    extern __shared__ char smem_raw[];
    Smem& s = *reinterpret_cast<Smem*>(smem_raw);
    const int tid = threadIdx.x;
    const int b = blockIdx.x;
    const int d = tid & 63;
    const int tr = tid >> 6;   // 0..3

    const float* ib = P.in + (size_t)b * SLN * FDIM;

    // ---- phase 0: load+normalize input, bias, rope cos/sin ----
    for (int idx = tid; idx < SLN * FDIM; idx += 256) {
        int t = idx / FDIM, c = idx % FDIM;
        float v = ib[idx];
        if (c < 8 || c == 10) {
            int f = (c < 8) ? c : 8;
            v = (v - g_mean[f]) * g_rstd[f] * P.gamma[f] + P.beta[f];
        }
        s.in[t][c] = v;
    }
    for (int idx = tid; idx < 48; idx += 256) s.bias[idx] = -P.dists[(size_t)b * SLN + idx];
    for (int idx = tid; idx < SLN * 4; idx += 256) {
        int t = idx >> 2, j = idx & 3;
        float x = ib[t * FDIM + 8], y = ib[t * FDIM + 9];  // raw cols 8,9
        float ang = (j == 0) ? 10.f * x : (j == 1) ? 10.f * y : (j == 2) ? x : y;
        s.cs[t][j] = cosf(ang);
        s.sn[t][j] = sinf(ang);
    }
    __syncthreads();

    // ---- x embed: tanhshrink(in8 @ w1 + b1) @ w2 + b2 ----
    {
        float w[8];
#pragma unroll
        for (int k = 0; k < 8; k++) w[k] = P.xe_w1[k * 64 + d];
        float b1 = P.xe_b1[d];
        for (int t = tr; t < SLN; t += 4) {
            float acc = b1;
#pragma unroll
            for (int k = 0; k < 8; k++) acc += s.in[t][k] * w[k];
            s.u.tmp[t][d] = acc - tanhf(acc);
        }
    }
    __syncthreads();
    {
        float w[64];
#pragma unroll
        for (int k = 0; k < 64; k++) w[k] = P.xe_w2[k * 64 + d];
        float b2 = P.xe_b2[d];
        for (int t = tr; t < SLN; t += 4)
            s.xe[t][d] = b2 + dot64(s.u.tmp[t], w);
    }
    __syncthreads();

    // ---- y embed (48 rows) + learnable last row ----
    {
        float w1 = P.ye_w1[d], b1 = P.ye_b1[d];
        for (int t = tr; t < 48; t += 4) {
            float acc = s.in[t][10] * w1 + b1;
            s.u.tmp[t][d] = acc - tanhf(acc);
        }
    }
    __syncthreads();
    {
        float w[64];
#pragma unroll
        for (int k = 0; k < 64; k++) w[k] = P.ye_w2[k * 64 + d];
        float b2 = P.ye_b2[d];
        for (int t = tr; t < 48; t += 4)
            s.ye[t][d] = b2 + dot64(s.u.tmp[t], w);
        if (tr == 0) s.ye[48][d] = P.learnable_y[d];
    }
    __syncthreads();

    const float scale = 0.35355339059327373f;  // 1/sqrt(8)

    for (int str = 0; str < 2; ++str) {
        const float (*ctx)[64] = (str == 0) ? (const float (*)[64])s.xe
                                            : (const float (*)[64])s.ye;
        // init H
        s.H[tr][d] = P.hidden_tokens[tr * 64 + d];
        __syncthreads();

        for (int l = 0; l < 2; ++l) {
            const int woff = (l * 2 + str) * 4096;
            // K raw projection
            {
                float w[64];
#pragma unroll
                for (int k = 0; k < 64; k++) w[k] = P.Wk[woff + k * 64 + d];
                for (int t = tr; t < 48; t += 4) s.K[t][d] = dot64(ctx[t], w);
            }
            // V projection
            {
                float w[64];
#pragma unroll
                for (int k = 0; k < 64; k++) w[k] = P.Wv[woff + k * 64 + d];
                for (int t = tr; t < 48; t += 4) s.V[t][d] = dot64(ctx[t], w);
            }
            // q projection (row = tr)
            {
                float acc = 0.f;
#pragma unroll
                for (int k = 0; k < 64; k++) acc += s.H[tr][k] * P.Wq[woff + k * 64 + d];
                s.u.a.q[tr][d] = acc;
            }
            __syncthreads();
            // rope on K (in-place, each pair owned by one thread)
            for (int idx = tid; idx < 48 * 32; idx += 256) {
                int t = idx >> 5, p = idx & 31, j = p & 3;
                float c = s.cs[t][j], sn = s.sn[t][j];
                float a0 = s.K[t][2 * p], a1 = s.K[t][2 * p + 1];
                s.K[t][2 * p]     = c * a0 - sn * a1;
                s.K[t][2 * p + 1] = sn * a0 + c * a1;
            }
            __syncthreads();
            // scores
            for (int idx = tid; idx < 32 * 48; idx += 256) {
                int t = idx % 48, r = idx / 48;
                int i = r & 3, h = r >> 2;
                float acc = 0.f;
#pragma unroll
                for (int dd = 0; dd < 8; dd++) acc += s.u.a.q[i][h * 8 + dd] * s.K[t][h * 8 + dd];
                s.u.a.sc[r][t] = acc * scale + s.bias[t];
            }
            __syncthreads();
            // softmax over 48 (32 rows x 8 lanes)
            {
                int row = tid >> 3, l8 = tid & 7;
                float* sc = s.u.a.sc[row];
                float m = -1e30f;
#pragma unroll
                for (int ii = 0; ii < 6; ii++) m = fmaxf(m, sc[l8 + 8 * ii]);
#pragma unroll
                for (int o = 1; o < 8; o <<= 1) m = fmaxf(m, __shfl_xor_sync(0xffffffffu, m, o));
                float e[6], sum = 0.f;
#pragma unroll
                for (int ii = 0; ii < 6; ii++) { e[ii] = __expf(sc[l8 + 8 * ii] - m); sum += e[ii]; }
#pragma unroll
                for (int o = 1; o < 8; o <<= 1) sum += __shfl_xor_sync(0xffffffffu, sum, o);
                float inv = 1.f / sum;
#pragma unroll
                for (int ii = 0; ii < 6; ii++) sc[l8 + 8 * ii] = e[ii] * inv;
            }
            __syncthreads();
            // o = merge(a @ v)
            {
                int h = d >> 3;
                const float* a = s.u.a.sc[h * 4 + tr];
                float acc = 0.f;
#pragma unroll
                for (int t = 0; t < 48; t++) acc += a[t] * s.V[t][d];
                s.u.a.o[tr][d] = acc;
            }
            __syncthreads();
            // H += o @ Wo
            {
                float w[64];
#pragma unroll
                for (int k = 0; k < 64; k++) w[k] = P.Wo[woff + k * 64 + d];
                s.H[tr][d] += dot64(s.u.a.o[tr], w);
            }
            __syncthreads();
        }

        // ---- cross attention ----
        {
            float acc1 = 0.f, acc2 = 0.f;
#pragma unroll
            for (int k = 0; k < 64; k++) {
                float hv = s.H[tr][k];
                acc1 += hv * P.Wk2[str * 4096 + k * 64 + d];
                acc2 += hv * P.Wv2[str * 4096 + k * 64 + d];
            }
            s.u.a.k2[tr][d] = acc1;
            s.u.a.v2[tr][d] = acc2;
            if (tid < 32) {   // roped query (pairs)
                int p = tid, j = p & 3;
                float r0 = 0.f, r1 = 0.f;
#pragma unroll
                for (int k = 0; k < 64; k++) {
                    float qv = ctx[48][k];
                    r0 += qv * P.Wq2[str * 4096 + k * 64 + 2 * p];
                    r1 += qv * P.Wq2[str * 4096 + k * 64 + 2 * p + 1];
                }
                float c = s.cs[48][j], sn = s.sn[48][j];
                s.u.a.qc[2 * p]     = c * r0 - sn * r1;
                s.u.a.qc[2 * p + 1] = sn * r0 + c * r1;
            }
        }
        __syncthreads();
        if (tid < 8) {   // scores over 4 tokens + softmax, per head
            int h = tid;
            float scv[4], m = -1e30f;
#pragma unroll
            for (int i = 0; i < 4; i++) {
                float acc = 0.f;
#pragma unroll
                for (int dd = 0; dd < 8; dd++) acc += s.u.a.qc[h * 8 + dd] * s.u.a.k2[i][h * 8 + dd];
                scv[i] = acc * scale;
                m = fmaxf(m, scv[i]);
            }
            float sum = 0.f;
#pragma unroll
            for (int i = 0; i < 4; i++) { scv[i] = __expf(scv[i] - m); sum += scv[i]; }
            float inv = 1.f / sum;
#pragma unroll
            for (int i = 0; i < 4; i++) s.u.a.a2[h * 4 + i] = scv[i] * inv;
        }
        __syncthreads();
        if (tid < 64) {
            int h = tid >> 3;
            float acc = 0.f;
#pragma unroll
            for (int i = 0; i < 4; i++) acc += s.u.a.a2[h * 4 + i] * s.u.a.v2[i][tid];
            s.u.a.outv[tid] = acc;
        }
        __syncthreads();
        if (tid < 64) {
            float acc = 0.f;
#pragma unroll
            for (int k = 0; k < 64; k++) acc += s.u.a.outv[k] * P.Wo2[str * 4096 + k * 64 + tid];
            enc[(size_t)b * DEC_IN + str * 64 + tid] = acc;
        }
        __syncthreads();
    }

    if (tid < 10) enc[(size_t)b * DEC_IN + 128 + tid] = s.in[48][tid];
}

// ---------------- decoder GEMMs ----------------
template <bool ACT>
__global__ void __launch_bounds__(256) gemm_kernel(const float* __restrict__ A, const float* __restrict__ B,
                                                   const float* __restrict__ bias, float* __restrict__ C,
                                                   int M, int N, int K) {
    const int BK = 16;
    __shared__ float As[BK][68];  // transposed A tile, padded
    __shared__ float Bs[BK][64];
    int tx = threadIdx.x & 15, ty = threadIdx.x >> 4;
    int bm = blockIdx.x * 64, bn = blockIdx.y * 64;
    float acc[4][4] = {};
    for (int k0 = 0; k0 < K; k0 += BK) {
        for (int idx = threadIdx.x; idx < 64 * BK; idx += 256) {
            int r = idx >> 4, kk = idx & 15;
            As[kk][r] = (k0 + kk < K) ? A[(size_t)(bm + r) * K + k0 + kk] : 0.f;
        }
        for (int idx = threadIdx.x; idx < BK * 64; idx += 256) {
            int kk = idx >> 6, c = idx & 63;
            Bs[kk][c] = (k0 + kk < K) ? B[(size_t)(k0 + kk) * N + bn + c] : 0.f;
        }
        __syncthreads();
#pragma unroll
        for (int kk = 0; kk < BK; kk++) {
            float4 av = *(const float4*)&As[kk][ty * 4];
            float4 bv = *(const float4*)&Bs[kk][tx * 4];
            float a[4] = {av.x, av.y, av.z, av.w};
            float bb[4] = {bv.x, bv.y, bv.z, bv.w};
#pragma unroll
            for (int i = 0; i < 4; i++)
#pragma unroll
                for (int j = 0; j < 4; j++) acc[i][j] += a[i] * bb[j];
        }
        __syncthreads();
    }
#pragma unroll
    for (int i = 0; i < 4; i++) {
        int r = bm + ty * 4 + i;
#pragma unroll
        for (int j = 0; j < 4; j++) {
            int c = bn + tx * 4 + j;
            float v = acc[i][j] + bias[c];
            if (ACT) v -= tanhf(v);
            C[(size_t)r * N + c] = v;
        }
    }
}

__global__ void __launch_bounds__(256) final_gemv(const float* __restrict__ H1, const float* __restrict__ w,
                                                  const float* __restrict__ b2, float* __restrict__ out) {
    int b = blockIdx.x * 8 + (threadIdx.x >> 5);
    int lane = threadIdx.x & 31;
    const float* row = H1 + (size_t)b * 256;
    float acc = 0.f;
#pragma unroll
    for (int k = lane; k < 256; k += 32) acc += row[k] * w[k];
#pragma unroll
    for (int o = 16; o; o >>= 1) acc += __shfl_down_sync(0xffffffffu, acc, o);
    if (lane == 0) out[b] = acc + b2[0];
}

// ---------------- launch ----------------
extern "C" void kernel_launch(void* const* d_in, const int* in_sizes, int n_in,
                              void* d_out, int out_size) {
    const float* in_t = (const float*)d_in[0];
    MainParams P;
    P.in = in_t;
    P.dists = (const float*)d_in[1];
    // d_in[2] target_position unused
    P.gamma = (const float*)d_in[3];  P.beta = (const float*)d_in[4];
    P.xe_w1 = (const float*)d_in[5];  P.xe_b1 = (const float*)d_in[6];
    P.xe_w2 = (const float*)d_in[7];  P.xe_b2 = (const float*)d_in[8];
    P.ye_w1 = (const float*)d_in[9];  P.ye_b1 = (const float*)d_in[10];
    P.ye_w2 = (const float*)d_in[11]; P.ye_b2 = (const float*)d_in[12];
    P.learnable_y = (const float*)d_in[13];
    P.hidden_tokens = (const float*)d_in[14];
    P.Wq = (const float*)d_in[15]; P.Wk = (const float*)d_in[16];
    P.Wv = (const float*)d_in[17]; P.Wo = (const float*)d_in[18];
    P.Wq2 = (const float*)d_in[19]; P.Wk2 = (const float*)d_in[20];
    P.Wv2 = (const float*)d_in[21]; P.Wo2 = (const float*)d_in[22];
    const float* dec_w0 = (const float*)d_in[23];
    const float* dec_b0 = (const float*)d_in[24];
    const float* dec_w1 = (const float*)d_in[25];
    const float* dec_b1 = (const float*)d_in[26];
    const float* dec_w2 = (const float*)d_in[27];
    const float* dec_b2 = (const float*)d_in[28];
    float* out = (float*)d_out;

    float *enc, *h0, *h1;
    cudaGetSymbolAddress((void**)&enc, g_enc);
    cudaGetSymbolAddress((void**)&h0, g_h0);
    cudaGetSymbolAddress((void**)&h1, g_h1);

    cudaFuncSetAttribute((const void*)k_main, cudaFuncAttributeMaxDynamicSharedMemorySize,
                         (int)sizeof(Smem));

    bn_zero_kernel<<<1, 32>>>();
    bn_acc_kernel<<<256, 256>>>(in_t);
    bn_fin_kernel<<<1, 32>>>();
    k_main<<<BSZ, 256, sizeof(Smem)>>>(P, enc);
    gemm_kernel<true><<<dim3(BSZ / 64, 512 / 64), 256>>>(enc, dec_w0, dec_b0, h0, BSZ, 512, DEC_IN);
    gemm_kernel<true><<<dim3(BSZ / 64, 256 / 64), 256>>>(h0, dec_w1, dec_b1, h1, BSZ, 256, 512);
    final_gemv<<<BSZ / 8, 256>>>(h1, dec_w2, dec_b2, out);
}

// round 2
// speedup vs baseline: 1.1393x; 1.1393x over previous
#include <cuda_runtime.h>
#include <math.h>

#define BSZ 8192
#define SLN 49
#define FDIM 11
#define DEC_IN 138

typedef unsigned long long ull;

__device__ __forceinline__ void fma2(ull& d, ull a, ull b) {
    asm("fma.rn.f32x2 %0, %1, %2, %0;" : "+l"(d) : "l"(a), "l"(b));
}
__device__ __forceinline__ ull pack2(float x, float y) {
    ull u; asm("mov.b64 %0, {%1, %2};" : "=l"(u) : "f"(x), "f"(y)); return u;
}
__device__ __forceinline__ float2 unpack2(ull u) {
    float2 v; asm("mov.b64 {%0, %1}, %2;" : "=f"(v.x), "=f"(v.y) : "l"(u)); return v;
}

// ---------------- device scratch ----------------
__device__ float g_sum[9];
__device__ float g_sumsq[9];
__device__ float g_mean[9];
__device__ float g_rstd[9];
__device__ float g_enc[BSZ * DEC_IN];
__device__ float g_h0[BSZ * 512];
__device__ float g_h1[BSZ * 256];

// ---------------- batch-norm statistics ----------------
__global__ void bn_zero_kernel() {
    if (threadIdx.x < 9) { g_sum[threadIdx.x] = 0.f; g_sumsq[threadIdx.x] = 0.f; }
}

__global__ void bn_acc_kernel(const float* __restrict__ in) {
    float ls[9], lq[9];
#pragma unroll
    for (int f = 0; f < 9; f++) { ls[f] = 0.f; lq[f] = 0.f; }
    int idx0 = blockIdx.x * blockDim.x + threadIdx.x;
    for (int r = idx0; r < BSZ * SLN; r += gridDim.x * blockDim.x) {
        const float* p = in + (size_t)r * FDIM;
#pragma unroll
        for (int f = 0; f < 9; f++) {
            float v = p[f < 8 ? f : 10];
            ls[f] += v; lq[f] += v * v;
        }
    }
#pragma unroll
    for (int f = 0; f < 9; f++) {
#pragma unroll
        for (int o = 16; o; o >>= 1) {
            ls[f] += __shfl_down_sync(0xffffffffu, ls[f], o);
            lq[f] += __shfl_down_sync(0xffffffffu, lq[f], o);
        }
    }
    if ((threadIdx.x & 31) == 0) {
#pragma unroll
        for (int f = 0; f < 9; f++) {
            atomicAdd(&g_sum[f], ls[f]);
            atomicAdd(&g_sumsq[f], lq[f]);
        }
    }
}

__global__ void bn_fin_kernel() {
    int f = threadIdx.x;
    if (f < 9) {
        float n = (float)(BSZ * SLN);
        float mu = g_sum[f] / n;
        float var = g_sumsq[f] / n - mu * mu;
        g_mean[f] = mu;
        g_rstd[f] = rsqrtf(var + 1e-5f);
    }
}

// ---------------- main per-element transformer kernel ----------------
struct MainParams {
    const float *in, *dists, *gamma, *beta;
    const float *xe_w1, *xe_b1, *xe_w2, *xe_b2;
    const float *ye_w1, *ye_b1, *ye_w2, *ye_b2;
    const float *learnable_y, *hidden_tokens;
    const float *Wq, *Wk, *Wv, *Wo, *Wq2, *Wk2, *Wv2, *Wo2;
};

#define TSTR 52   // transposed-ctx row stride (floats); 52*4B, 16B aligned

struct __align__(16) Smem {
    float in[SLN][12];
    float cs[SLN][4];
    float sn[SLN][4];
    float bias[48];
    float xeT[64][TSTR];   // transposed: xeT[k][t]
    float yeT[64][TSTR];
    float K[48][64];
    float V[48][64];
    float H[4][64];
    union {
        float tmpT[64][TSTR];  // transposed embed intermediate
        struct {
            float sc[32][48];
            float q[4][64];
            float o[4][64];
            float k2[4][64];
            float v2[4][64];
            float qc[64];
            float outv[64];
            float a2[32];
        } a;
    } u;
};

__global__ void __launch_bounds__(256, 3) k_main(MainParams P, float* __restrict__ enc) {
    extern __shared__ char smem_raw[];
    Smem& s = *reinterpret_cast<Smem*>(smem_raw);
    const int tid = threadIdx.x;
    const int b = blockIdx.x;
    const int c = tid & 63;    // column 0..63
    const int g = tid >> 6;    // row-group 0..3

    const float* ib = P.in + (size_t)b * SLN * FDIM;

    // ---- phase 0: load+normalize input, bias, rope cos/sin ----
    for (int idx = tid; idx < SLN * FDIM; idx += 256) {
        int t = idx / FDIM, cc = idx % FDIM;
        float v = ib[idx];
        if (cc < 8 || cc == 10) {
            int f = (cc < 8) ? cc : 8;
            v = (v - g_mean[f]) * g_rstd[f] * P.gamma[f] + P.beta[f];
        }
        s.in[t][cc] = v;
    }
    for (int idx = tid; idx < 48; idx += 256) s.bias[idx] = -P.dists[(size_t)b * SLN + idx];
    for (int idx = tid; idx < SLN * 4; idx += 256) {
        int t = idx >> 2, j = idx & 3;
        float x = ib[t * FDIM + 8], y = ib[t * FDIM + 9];
        float ang = (j == 0) ? 10.f * x : (j == 1) ? 10.f * y : (j == 2) ? x : y;
        s.cs[t][j] = cosf(ang);
        s.sn[t][j] = sinf(ang);
    }
    __syncthreads();

    // ---- x embed stage1: tanhshrink(in8 @ w1 + b1) -> tmpT (transposed) ----
    {
        float w[8];
#pragma unroll
        for (int k = 0; k < 8; k++) w[k] = P.xe_w1[k * 64 + c];
        float b1 = P.xe_b1[c];
        for (int t = g; t < SLN; t += 4) {
            float acc = b1;
#pragma unroll
            for (int k = 0; k < 8; k++) acc += s.in[t][k] * w[k];
            s.u.tmpT[c][t] = acc - tanhf(acc);
        }
    }
    __syncthreads();
    // ---- x embed stage2: tmpT @ w2 + b2 -> xeT (transposed), packed f32x2 ----
    {
        const float b2v = P.xe_b2[c];
        const int t0 = g * 12;
        ull acc[6];
#pragma unroll
        for (int p = 0; p < 6; p++) acc[p] = pack2(b2v, b2v);
        const float* W = P.xe_w2 + c;
        for (int kc = 0; kc < 64; kc += 8) {
            float w[8];
#pragma unroll
            for (int j = 0; j < 8; j++) w[j] = W[(kc + j) * 64];
#pragma unroll
            for (int j = 0; j < 8; j++) {
                ull w2 = pack2(w[j], w[j]);
                const ulonglong2* act = reinterpret_cast<const ulonglong2*>(&s.u.tmpT[kc + j][t0]);
#pragma unroll
                for (int p = 0; p < 3; p++) {
                    ulonglong2 a4 = act[p];
                    fma2(acc[2 * p], a4.x, w2);
                    fma2(acc[2 * p + 1], a4.y, w2);
                }
            }
        }
#pragma unroll
        for (int p = 0; p < 6; p++)
            *reinterpret_cast<float2*>(&s.xeT[c][t0 + 2 * p]) = unpack2(acc[p]);
        if (g == 0) {   // tail row 48
            float acc48 = b2v;
            for (int k = 0; k < 64; k++) acc48 += s.u.tmpT[k][48] * P.xe_w2[k * 64 + c];
            s.xeT[c][48] = acc48;
        }
    }
    __syncthreads();

    // ---- y embed stage1 (48 rows) -> tmpT ----
    {
        float w1 = P.ye_w1[c], b1 = P.ye_b1[c];
        for (int t = g; t < 48; t += 4) {
            float acc = s.in[t][10] * w1 + b1;
            s.u.tmpT[c][t] = acc - tanhf(acc);
        }
    }
    __syncthreads();
    // ---- y embed stage2 -> yeT, packed ----
    {
        const float b2v = P.ye_b2[c];
        const int t0 = g * 12;
        ull acc[6];
#pragma unroll
        for (int p = 0; p < 6; p++) acc[p] = pack2(b2v, b2v);
        const float* W = P.ye_w2 + c;
        for (int kc = 0; kc < 64; kc += 8) {
            float w[8];
#pragma unroll
            for (int j = 0; j < 8; j++) w[j] = W[(kc + j) * 64];
#pragma unroll
            for (int j = 0; j < 8; j++) {
                ull w2 = pack2(w[j], w[j]);
                const ulonglong2* act = reinterpret_cast<const ulonglong2*>(&s.u.tmpT[kc + j][t0]);
#pragma unroll
                for (int p = 0; p < 3; p++) {
                    ulonglong2 a4 = act[p];
                    fma2(acc[2 * p], a4.x, w2);
                    fma2(acc[2 * p + 1], a4.y, w2);
                }
            }
        }
#pragma unroll
        for (int p = 0; p < 6; p++)
            *reinterpret_cast<float2*>(&s.yeT[c][t0 + 2 * p]) = unpack2(acc[p]);
        if (g == 0) s.yeT[c][48] = P.learnable_y[c];
    }
    __syncthreads();

    const float scale = 0.35355339059327373f;  // 1/sqrt(8)

#pragma unroll 1
    for (int str = 0; str < 2; ++str) {
        const float* ctxT = (str == 0) ? &s.xeT[0][0] : &s.yeT[0][0];
        // init H
        s.H[g][c] = P.hidden_tokens[g * 64 + c];
        __syncthreads();

#pragma unroll 1
        for (int l = 0; l < 2; ++l) {
            const int woff = (l * 2 + str) * 4096;
            // ---- merged K+V projection, packed f32x2, transposed ctx ----
            {
                const int t0 = g * 12;
                ull accK[6], accV[6];
#pragma unroll
                for (int p = 0; p < 6; p++) { accK[p] = 0ull; accV[p] = 0ull; }
                const float* WkB = P.Wk + woff + c;
                const float* WvB = P.Wv + woff + c;
                for (int kc = 0; kc < 64; kc += 8) {
                    float wk[8], wv[8];
#pragma unroll
                    for (int j = 0; j < 8; j++) { wk[j] = WkB[(kc + j) * 64]; wv[j] = WvB[(kc + j) * 64]; }
#pragma unroll
                    for (int j = 0; j < 8; j++) {
                        ull wk2 = pack2(wk[j], wk[j]);
                        ull wv2 = pack2(wv[j], wv[j]);
                        const ulonglong2* act = reinterpret_cast<const ulonglong2*>(&ctxT[(kc + j) * TSTR + t0]);
#pragma unroll
                        for (int p = 0; p < 3; p++) {
                            ulonglong2 a4 = act[p];
                            fma2(accK[2 * p], a4.x, wk2);
                            fma2(accK[2 * p + 1], a4.y, wk2);
                            fma2(accV[2 * p], a4.x, wv2);
                            fma2(accV[2 * p + 1], a4.y, wv2);
                        }
                    }
                }
#pragma unroll
                for (int p = 0; p < 6; p++) {
                    float2 kv = unpack2(accK[p]);
                    s.K[t0 + 2 * p][c] = kv.x;
                    s.K[t0 + 2 * p + 1][c] = kv.y;
                    float2 vv = unpack2(accV[p]);
                    s.V[t0 + 2 * p][c] = vv.x;
                    s.V[t0 + 2 * p + 1][c] = vv.y;
                }
            }
            // ---- q projection (row = g), chunked ----
            {
                float acc = 0.f;
#pragma unroll
                for (int kc = 0; kc < 64; kc += 16) {
                    float w[16];
#pragma unroll
                    for (int j = 0; j < 16; j++) w[j] = P.Wq[woff + (kc + j) * 64 + c];
                    const float4* h4 = reinterpret_cast<const float4*>(&s.H[g][kc]);
#pragma unroll
                    for (int q4 = 0; q4 < 4; q4++) {
                        float4 hv = h4[q4];
                        acc += hv.x * w[4 * q4] + hv.y * w[4 * q4 + 1] + hv.z * w[4 * q4 + 2] + hv.w * w[4 * q4 + 3];
                    }
                }
                s.u.a.q[g][c] = acc;
            }
            __syncthreads();
            // ---- rope on K ----
            for (int idx = tid; idx < 48 * 32; idx += 256) {
                int t = idx >> 5, p = idx & 31, j = p & 3;
                float cc = s.cs[t][j], sn = s.sn[t][j];
                float a0 = s.K[t][2 * p], a1 = s.K[t][2 * p + 1];
                s.K[t][2 * p]     = cc * a0 - sn * a1;
                s.K[t][2 * p + 1] = sn * a0 + cc * a1;
            }
            __syncthreads();
            // ---- scores ----
            for (int idx = tid; idx < 32 * 48; idx += 256) {
                int t = idx % 48, r = idx / 48;
                int i = r & 3, h = r >> 2;
                const float4* q4 = reinterpret_cast<const float4*>(&s.u.a.q[i][h * 8]);
                const float4* k4 = reinterpret_cast<const float4*>(&s.K[t][h * 8]);
                float4 qa = q4[0], qb = q4[1], ka = k4[0], kb = k4[1];
                float acc = qa.x * ka.x + qa.y * ka.y + qa.z * ka.z + qa.w * ka.w
                          + qb.x * kb.x + qb.y * kb.y + qb.z * kb.z + qb.w * kb.w;
                s.u.a.sc[r][t] = acc * scale + s.bias[t];
            }
            __syncthreads();
            // ---- softmax over 48 ----
            {
                int row = tid >> 3, l8 = tid & 7;
                float* sc = s.u.a.sc[row];
                float m = -1e30f;
#pragma unroll
                for (int ii = 0; ii < 6; ii++) m = fmaxf(m, sc[l8 + 8 * ii]);
#pragma unroll
                for (int o = 1; o < 8; o <<= 1) m = fmaxf(m, __shfl_xor_sync(0xffffffffu, m, o));
                float e[6], sum = 0.f;
#pragma unroll
                for (int ii = 0; ii < 6; ii++) { e[ii] = __expf(sc[l8 + 8 * ii] - m); sum += e[ii]; }
#pragma unroll
                for (int o = 1; o < 8; o <<= 1) sum += __shfl_xor_sync(0xffffffffu, sum, o);
                float inv = 1.f / sum;
#pragma unroll
                for (int ii = 0; ii < 6; ii++) sc[l8 + 8 * ii] = e[ii] * inv;
            }
            __syncthreads();
            // ---- o = merge(a @ v) ----
            {
                int h = c >> 3;
                const float* a = s.u.a.sc[h * 4 + g];
                float acc = 0.f;
#pragma unroll
                for (int t = 0; t < 48; t++) acc += a[t] * s.V[t][c];
                s.u.a.o[g][c] = acc;
            }
            __syncthreads();
            // ---- H += o @ Wo, chunked ----
            {
                float acc = 0.f;
#pragma unroll
                for (int kc = 0; kc < 64; kc += 16) {
                    float w[16];
#pragma unroll
                    for (int j = 0; j < 16; j++) w[j] = P.Wo[woff + (kc + j) * 64 + c];
                    const float4* o4 = reinterpret_cast<const float4*>(&s.u.a.o[g][kc]);
#pragma unroll
                    for (int q4 = 0; q4 < 4; q4++) {
                        float4 ov = o4[q4];
                        acc += ov.x * w[4 * q4] + ov.y * w[4 * q4 + 1] + ov.z * w[4 * q4 + 2] + ov.w * w[4 * q4 + 3];
                    }
                }
                s.H[g][c] += acc;
            }
            __syncthreads();
        }

        // ---- cross attention ----
        {
            float acc1 = 0.f, acc2 = 0.f;
#pragma unroll
            for (int kc = 0; kc < 64; kc += 8) {
                float wk[8], wv[8];
#pragma unroll
                for (int j = 0; j < 8; j++) {
                    wk[j] = P.Wk2[str * 4096 + (kc + j) * 64 + c];
                    wv[j] = P.Wv2[str * 4096 + (kc + j) * 64 + c];
                }
#pragma unroll
                for (int j = 0; j < 8; j++) {
                    float hv = s.H[g][kc + j];
                    acc1 += hv * wk[j];
                    acc2 += hv * wv[j];
                }
            }
            s.u.a.k2[g][c] = acc1;
            s.u.a.v2[g][c] = acc2;
            if (tid < 32) {
                int p = tid, j = p & 3;
                float r0 = 0.f, r1 = 0.f;
#pragma unroll
                for (int k = 0; k < 64; k++) {
                    float qv = ctxT[k * TSTR + 48];
                    r0 += qv * P.Wq2[str * 4096 + k * 64 + 2 * p];
                    r1 += qv * P.Wq2[str * 4096 + k * 64 + 2 * p + 1];
                }
                float cc = s.cs[48][j], sn = s.sn[48][j];
                s.u.a.qc[2 * p]     = cc * r0 - sn * r1;
                s.u.a.qc[2 * p + 1] = sn * r0 + cc * r1;
            }
        }
        __syncthreads();
        if (tid < 8) {
            int h = tid;
            float scv[4], m = -1e30f;
#pragma unroll
            for (int i = 0; i < 4; i++) {
                float acc = 0.f;
#pragma unroll
                for (int dd = 0; dd < 8; dd++) acc += s.u.a.qc[h * 8 + dd] * s.u.a.k2[i][h * 8 + dd];
                scv[i] = acc * scale;
                m = fmaxf(m, scv[i]);
            }
            float sum = 0.f;
#pragma unroll
            for (int i = 0; i < 4; i++) { scv[i] = __expf(scv[i] - m); sum += scv[i]; }
            float inv = 1.f / sum;
#pragma unroll
            for (int i = 0; i < 4; i++) s.u.a.a2[h * 4 + i] = scv[i] * inv;
        }
        __syncthreads();
        if (tid < 64) {
            int h = tid >> 3;
            float acc = 0.f;
#pragma unroll
            for (int i = 0; i < 4; i++) acc += s.u.a.a2[h * 4 + i] * s.u.a.v2[i][tid];
            s.u.a.outv[tid] = acc;
        }
        __syncthreads();
        if (tid < 64) {
            float acc = 0.f;
#pragma unroll
            for (int k = 0; k < 64; k++) acc += s.u.a.outv[k] * P.Wo2[str * 4096 + k * 64 + tid];
            enc[(size_t)b * DEC_IN + str * 64 + tid] = acc;
        }
        __syncthreads();
    }

    if (tid < 10) enc[(size_t)b * DEC_IN + 128 + tid] = s.in[48][tid];
}

// ---------------- decoder GEMMs ----------------
template <bool ACT>
__global__ void __launch_bounds__(256) gemm_kernel(const float* __restrict__ A, const float* __restrict__ B,
                                                   const float* __restrict__ bias, float* __restrict__ C,
                                                   int M, int N, int K) {
    const int BK = 16;
    __shared__ float As[BK][68];
    __shared__ float Bs[BK][64];
    int tx = threadIdx.x & 15, ty = threadIdx.x >> 4;
    int bm = blockIdx.x * 64, bn = blockIdx.y * 64;
    float acc[4][4] = {};
    for (int k0 = 0; k0 < K; k0 += BK) {
        for (int idx = threadIdx.x; idx < 64 * BK; idx += 256) {
            int r = idx >> 4, kk = idx & 15;
            As[kk][r] = (k0 + kk < K) ? A[(size_t)(bm + r) * K + k0 + kk] : 0.f;
        }
        for (int idx = threadIdx.x; idx < BK * 64; idx += 256) {
            int kk = idx >> 6, cc = idx & 63;
            Bs[kk][cc] = (k0 + kk < K) ? B[(size_t)(k0 + kk) * N + bn + cc] : 0.f;
        }
        __syncthreads();
#pragma unroll
        for (int kk = 0; kk < BK; kk++) {
            float4 av = *(const float4*)&As[kk][ty * 4];
            float4 bv = *(const float4*)&Bs[kk][tx * 4];
            float a[4] = {av.x, av.y, av.z, av.w};
            float bb[4] = {bv.x, bv.y, bv.z, bv.w};
#pragma unroll
            for (int i = 0; i < 4; i++)
#pragma unroll
                for (int j = 0; j < 4; j++) acc[i][j] += a[i] * bb[j];
        }
        __syncthreads();
    }
#pragma unroll
    for (int i = 0; i < 4; i++) {
        int r = bm + ty * 4 + i;
#pragma unroll
        for (int j = 0; j < 4; j++) {
            int cc = bn + tx * 4 + j;
            float v = acc[i][j] + bias[cc];
            if (ACT) v -= tanhf(v);
            C[(size_t)r * N + cc] = v;
        }
    }
}

__global__ void __launch_bounds__(256) final_gemv(const float* __restrict__ H1, const float* __restrict__ w,
                                                  const float* __restrict__ b2, float* __restrict__ out) {
    int b = blockIdx.x * 8 + (threadIdx.x >> 5);
    int lane = threadIdx.x & 31;
    const float* row = H1 + (size_t)b * 256;
    float acc = 0.f;
#pragma unroll
    for (int k = lane; k < 256; k += 32) acc += row[k] * w[k];
#pragma unroll
    for (int o = 16; o; o >>= 1) acc += __shfl_down_sync(0xffffffffu, acc, o);
    if (lane == 0) out[b] = acc + b2[0];
}

// ---------------- launch ----------------
extern "C" void kernel_launch(void* const* d_in, const int* in_sizes, int n_in,
                              void* d_out, int out_size) {
    const float* in_t = (const float*)d_in[0];
    MainParams P;
    P.in = in_t;
    P.dists = (const float*)d_in[1];
    P.gamma = (const float*)d_in[3];  P.beta = (const float*)d_in[4];
    P.xe_w1 = (const float*)d_in[5];  P.xe_b1 = (const float*)d_in[6];
    P.xe_w2 = (const float*)d_in[7];  P.xe_b2 = (const float*)d_in[8];
    P.ye_w1 = (const float*)d_in[9];  P.ye_b1 = (const float*)d_in[10];
    P.ye_w2 = (const float*)d_in[11]; P.ye_b2 = (const float*)d_in[12];
    P.learnable_y = (const float*)d_in[13];
    P.hidden_tokens = (const float*)d_in[14];
    P.Wq = (const float*)d_in[15]; P.Wk = (const float*)d_in[16];
    P.Wv = (const float*)d_in[17]; P.Wo = (const float*)d_in[18];
    P.Wq2 = (const float*)d_in[19]; P.Wk2 = (const float*)d_in[20];
    P.Wv2 = (const float*)d_in[21]; P.Wo2 = (const float*)d_in[22];
    const float* dec_w0 = (const float*)d_in[23];
    const float* dec_b0 = (const float*)d_in[24];
    const float* dec_w1 = (const float*)d_in[25];
    const float* dec_b1 = (const float*)d_in[26];
    const float* dec_w2 = (const float*)d_in[27];
    const float* dec_b2 = (const float*)d_in[28];
    float* out = (float*)d_out;

    float *enc, *h0, *h1;
    cudaGetSymbolAddress((void**)&enc, g_enc);
    cudaGetSymbolAddress((void**)&h0, g_h0);
    cudaGetSymbolAddress((void**)&h1, g_h1);

    cudaFuncSetAttribute((const void*)k_main, cudaFuncAttributeMaxDynamicSharedMemorySize,
                         (int)sizeof(Smem));

    bn_zero_kernel<<<1, 32>>>();
    bn_acc_kernel<<<256, 256>>>(in_t);
    bn_fin_kernel<<<1, 32>>>();
    k_main<<<BSZ, 256, sizeof(Smem)>>>(P, enc);
    gemm_kernel<true><<<dim3(BSZ / 64, 512 / 64), 256>>>(enc, dec_w0, dec_b0, h0, BSZ, 512, DEC_IN);
    gemm_kernel<true><<<dim3(BSZ / 64, 256 / 64), 256>>>(h0, dec_w1, dec_b1, h1, BSZ, 256, 512);
    final_gemv<<<BSZ / 8, 256>>>(h1, dec_w2, dec_b2, out);
}

// round 3
// speedup vs baseline: 1.4232x; 1.2492x over previous
#include <cuda_runtime.h>
#include <math.h>

#define BSZ 8192
#define SLN 49
#define FDIM 11
#define DEC_IN 138

typedef unsigned long long ull;

__device__ __forceinline__ void fma2(ull& d, ull a, ull b) {
    asm("fma.rn.f32x2 %0, %1, %2, %0;" : "+l"(d) : "l"(a), "l"(b));
}
__device__ __forceinline__ ull pack2(float x, float y) {
    ull u; asm("mov.b64 %0, {%1, %2};" : "=l"(u) : "f"(x), "f"(y)); return u;
}
__device__ __forceinline__ float2 unpack2(ull u) {
    float2 v; asm("mov.b64 {%0, %1}, %2;" : "=f"(v.x), "=f"(v.y) : "l"(u)); return v;
}

// ---------------- device scratch ----------------
__device__ float g_sum[9];
__device__ float g_sumsq[9];
__device__ float g_mean[9];
__device__ float g_rstd[9];
__device__ float g_enc[BSZ * DEC_IN];
__device__ float g_h0[BSZ * 512];
__device__ float g_h1[BSZ * 256];

// ---------------- batch-norm statistics ----------------
__global__ void bn_zero_kernel() {
    if (threadIdx.x < 9) { g_sum[threadIdx.x] = 0.f; g_sumsq[threadIdx.x] = 0.f; }
}

__global__ void bn_acc_kernel(const float* __restrict__ in) {
    float ls[9], lq[9];
#pragma unroll
    for (int f = 0; f < 9; f++) { ls[f] = 0.f; lq[f] = 0.f; }
    int idx0 = blockIdx.x * blockDim.x + threadIdx.x;
    for (int r = idx0; r < BSZ * SLN; r += gridDim.x * blockDim.x) {
        const float* p = in + (size_t)r * FDIM;
#pragma unroll
        for (int f = 0; f < 9; f++) {
            float v = p[f < 8 ? f : 10];
            ls[f] += v; lq[f] += v * v;
        }
    }
#pragma unroll
    for (int f = 0; f < 9; f++) {
#pragma unroll
        for (int o = 16; o; o >>= 1) {
            ls[f] += __shfl_down_sync(0xffffffffu, ls[f], o);
            lq[f] += __shfl_down_sync(0xffffffffu, lq[f], o);
        }
    }
    if ((threadIdx.x & 31) == 0) {
#pragma unroll
        for (int f = 0; f < 9; f++) {
            atomicAdd(&g_sum[f], ls[f]);
            atomicAdd(&g_sumsq[f], lq[f]);
        }
    }
}

__global__ void bn_fin_kernel() {
    int f = threadIdx.x;
    if (f < 9) {
        float n = (float)(BSZ * SLN);
        float mu = g_sum[f] / n;
        float var = g_sumsq[f] / n - mu * mu;
        g_mean[f] = mu;
        g_rstd[f] = rsqrtf(var + 1e-5f);
    }
}

// ---------------- main per-element transformer kernel ----------------
struct MainParams {
    const float *in, *dists, *gamma, *beta;
    const float *xe_w1, *xe_b1, *xe_w2, *xe_b2;
    const float *ye_w1, *ye_b1, *ye_w2, *ye_b2;
    const float *learnable_y, *hidden_tokens;
    const float *Wq, *Wk, *Wv, *Wo, *Wq2, *Wk2, *Wv2, *Wo2;
};

#define TSTR 52   // transposed-ctx row stride (floats)
#define KSTR 50   // KT row stride (floats)
#define SCSTR 50  // sc row stride

struct __align__(16) Smem {
    float in[SLN][12];
    float cs[SLN][4];
    float sn[SLN][4];
    float bias[48];
    float xeT[64][TSTR];   // transposed: xeT[k][t]
    float yeT[64][TSTR];
    float KT[64][KSTR];    // transposed keys: KT[d][t]
    float V[48][64];
    float H[4][64];
    union {
        float tmpT[64][TSTR];  // transposed embed intermediate
        struct {
            float sc[32][SCSTR];  // attention weights [r][t]
            float q[4][64];
            float o[4][64];
            float o2[2][4][64];
            float k2[4][64];
            float v2[4][64];
            float qc[64];
            float outv[64];
            float a2[32];
        } a;
    } u;
};

__global__ void __launch_bounds__(256, 3) k_main(MainParams P, float* __restrict__ enc) {
    extern __shared__ char smem_raw[];
    Smem& s = *reinterpret_cast<Smem*>(smem_raw);
    const int tid = threadIdx.x;
    const int b = blockIdx.x;
    const int c = tid & 63;    // column 0..63
    const int g = tid >> 6;    // row-group 0..3

    const float* ib = P.in + (size_t)b * SLN * FDIM;

    // ---- phase 0: load+normalize input, bias, rope cos/sin ----
    for (int idx = tid; idx < SLN * FDIM; idx += 256) {
        int t = idx / FDIM, cc = idx % FDIM;
        float v = ib[idx];
        if (cc < 8 || cc == 10) {
            int f = (cc < 8) ? cc : 8;
            v = (v - g_mean[f]) * g_rstd[f] * P.gamma[f] + P.beta[f];
        }
        s.in[t][cc] = v;
    }
    for (int idx = tid; idx < 48; idx += 256) s.bias[idx] = -P.dists[(size_t)b * SLN + idx];
    for (int idx = tid; idx < SLN * 4; idx += 256) {
        int t = idx >> 2, j = idx & 3;
        float x = ib[t * FDIM + 8], y = ib[t * FDIM + 9];
        float ang = (j == 0) ? 10.f * x : (j == 1) ? 10.f * y : (j == 2) ? x : y;
        s.cs[t][j] = cosf(ang);
        s.sn[t][j] = sinf(ang);
    }
    __syncthreads();

    // ---- x embed stage1 ----
    {
        float w[8];
#pragma unroll
        for (int k = 0; k < 8; k++) w[k] = P.xe_w1[k * 64 + c];
        float b1 = P.xe_b1[c];
        for (int t = g; t < SLN; t += 4) {
            float acc = b1;
#pragma unroll
            for (int k = 0; k < 8; k++) acc += s.in[t][k] * w[k];
            s.u.tmpT[c][t] = acc - tanhf(acc);
        }
    }
    __syncthreads();
    // ---- x embed stage2 ----
    {
        const float b2v = P.xe_b2[c];
        const int t0 = g * 12;
        ull acc[6];
#pragma unroll
        for (int p = 0; p < 6; p++) acc[p] = pack2(b2v, b2v);
        const float* W = P.xe_w2 + c;
        for (int kc = 0; kc < 64; kc += 8) {
            float w[8];
#pragma unroll
            for (int j = 0; j < 8; j++) w[j] = W[(kc + j) * 64];
#pragma unroll
            for (int j = 0; j < 8; j++) {
                ull w2 = pack2(w[j], w[j]);
                const ulonglong2* act = reinterpret_cast<const ulonglong2*>(&s.u.tmpT[kc + j][t0]);
#pragma unroll
                for (int p = 0; p < 3; p++) {
                    ulonglong2 a4 = act[p];
                    fma2(acc[2 * p], a4.x, w2);
                    fma2(acc[2 * p + 1], a4.y, w2);
                }
            }
        }
#pragma unroll
        for (int p = 0; p < 6; p++)
            *reinterpret_cast<float2*>(&s.xeT[c][t0 + 2 * p]) = unpack2(acc[p]);
        if (g == 0) {
            float acc48 = b2v;
            for (int k = 0; k < 64; k++) acc48 += s.u.tmpT[k][48] * P.xe_w2[k * 64 + c];
            s.xeT[c][48] = acc48;
        }
    }
    __syncthreads();

    // ---- y embed stage1 ----
    {
        float w1 = P.ye_w1[c], b1 = P.ye_b1[c];
        for (int t = g; t < 48; t += 4) {
            float acc = s.in[t][10] * w1 + b1;
            s.u.tmpT[c][t] = acc - tanhf(acc);
        }
    }
    __syncthreads();
    // ---- y embed stage2 ----
    {
        const float b2v = P.ye_b2[c];
        const int t0 = g * 12;
        ull acc[6];
#pragma unroll
        for (int p = 0; p < 6; p++) acc[p] = pack2(b2v, b2v);
        const float* W = P.ye_w2 + c;
        for (int kc = 0; kc < 64; kc += 8) {
            float w[8];
#pragma unroll
            for (int j = 0; j < 8; j++) w[j] = W[(kc + j) * 64];
#pragma unroll
            for (int j = 0; j < 8; j++) {
                ull w2 = pack2(w[j], w[j]);
                const ulonglong2* act = reinterpret_cast<const ulonglong2*>(&s.u.tmpT[kc + j][t0]);
#pragma unroll
                for (int p = 0; p < 3; p++) {
                    ulonglong2 a4 = act[p];
                    fma2(acc[2 * p], a4.x, w2);
                    fma2(acc[2 * p + 1], a4.y, w2);
                }
            }
        }
#pragma unroll
        for (int p = 0; p < 6; p++)
            *reinterpret_cast<float2*>(&s.yeT[c][t0 + 2 * p]) = unpack2(acc[p]);
        if (g == 0) s.yeT[c][48] = P.learnable_y[c];
    }
    __syncthreads();

    const float scale = 0.35355339059327373f;  // 1/sqrt(8)

#pragma unroll 1
    for (int str = 0; str < 2; ++str) {
        const float* ctxT = (str == 0) ? &s.xeT[0][0] : &s.yeT[0][0];
        s.H[g][c] = P.hidden_tokens[g * 64 + c];
        __syncthreads();

#pragma unroll 1
        for (int l = 0; l < 2; ++l) {
            const int woff = (l * 2 + str) * 4096;
            // ---- merged K+V projection (K stored transposed) ----
            {
                const int t0 = g * 12;
                ull accK[6], accV[6];
#pragma unroll
                for (int p = 0; p < 6; p++) { accK[p] = 0ull; accV[p] = 0ull; }
                const float* WkB = P.Wk + woff + c;
                const float* WvB = P.Wv + woff + c;
                for (int kc = 0; kc < 64; kc += 8) {
                    float wk[8], wv[8];
#pragma unroll
                    for (int j = 0; j < 8; j++) { wk[j] = WkB[(kc + j) * 64]; wv[j] = WvB[(kc + j) * 64]; }
#pragma unroll
                    for (int j = 0; j < 8; j++) {
                        ull wk2 = pack2(wk[j], wk[j]);
                        ull wv2 = pack2(wv[j], wv[j]);
                        const ulonglong2* act = reinterpret_cast<const ulonglong2*>(&ctxT[(kc + j) * TSTR + t0]);
#pragma unroll
                        for (int p = 0; p < 3; p++) {
                            ulonglong2 a4 = act[p];
                            fma2(accK[2 * p], a4.x, wk2);
                            fma2(accK[2 * p + 1], a4.y, wk2);
                            fma2(accV[2 * p], a4.x, wv2);
                            fma2(accV[2 * p + 1], a4.y, wv2);
                        }
                    }
                }
                // K transposed store: KT[c][t0..t0+11]
#pragma unroll
                for (int p = 0; p < 6; p++)
                    *reinterpret_cast<float2*>(&s.KT[c][t0 + 2 * p]) = unpack2(accK[p]);
#pragma unroll
                for (int p = 0; p < 6; p++) {
                    float2 vv = unpack2(accV[p]);
                    s.V[t0 + 2 * p][c] = vv.x;
                    s.V[t0 + 2 * p + 1][c] = vv.y;
                }
            }
            // ---- q projection ----
            {
                float acc = 0.f;
#pragma unroll
                for (int kc = 0; kc < 64; kc += 16) {
                    float w[16];
#pragma unroll
                    for (int j = 0; j < 16; j++) w[j] = P.Wq[woff + (kc + j) * 64 + c];
                    const float4* h4 = reinterpret_cast<const float4*>(&s.H[g][kc]);
#pragma unroll
                    for (int q4 = 0; q4 < 4; q4++) {
                        float4 hv = h4[q4];
                        acc += hv.x * w[4 * q4] + hv.y * w[4 * q4 + 1] + hv.z * w[4 * q4 + 2] + hv.w * w[4 * q4 + 3];
                    }
                }
                s.u.a.q[g][c] = acc;
            }
            __syncthreads();
            // ---- rope on KT: thread = (pair p=tid>>3, tg=tid&7) ----
            {
                int p = tid >> 3, tg = tid & 7, j = p & 3;
                int t0 = tg * 6;
                float2 e0[3], e1[3];
#pragma unroll
                for (int q2 = 0; q2 < 3; q2++) {
                    e0[q2] = *reinterpret_cast<float2*>(&s.KT[2 * p][t0 + 2 * q2]);
                    e1[q2] = *reinterpret_cast<float2*>(&s.KT[2 * p + 1][t0 + 2 * q2]);
                }
#pragma unroll
                for (int q2 = 0; q2 < 3; q2++) {
#pragma unroll
                    for (int e = 0; e < 2; e++) {
                        int t = t0 + 2 * q2 + e;
                        float cc = s.cs[t][j], sn = s.sn[t][j];
                        float a0 = (e == 0) ? e0[q2].x : e0[q2].y;
                        float a1 = (e == 0) ? e1[q2].x : e1[q2].y;
                        float r0 = cc * a0 - sn * a1;
                        float r1 = sn * a0 + cc * a1;
                        if (e == 0) { e0[q2].x = r0; e1[q2].x = r1; }
                        else        { e0[q2].y = r0; e1[q2].y = r1; }
                    }
                }
#pragma unroll
                for (int q2 = 0; q2 < 3; q2++) {
                    *reinterpret_cast<float2*>(&s.KT[2 * p][t0 + 2 * q2]) = e0[q2];
                    *reinterpret_cast<float2*>(&s.KT[2 * p + 1][t0 + 2 * q2]) = e1[q2];
                }
            }
            __syncthreads();
            // ---- fused scores + softmax: thread = (row r=tid>>3, l8=tid&7) ----
            {
                int r = tid >> 3, l8 = tid & 7;
                int h = r >> 2, i = r & 3;
                int t0 = l8 * 6;
                ull acc[3] = {0ull, 0ull, 0ull};
#pragma unroll
                for (int d = 0; d < 8; d++) {
                    float qv = s.u.a.q[i][h * 8 + d];
                    ull q2 = pack2(qv, qv);
                    const float2* kt = reinterpret_cast<const float2*>(&s.KT[h * 8 + d][t0]);
#pragma unroll
                    for (int p = 0; p < 3; p++) {
                        float2 kv = kt[p];
                        fma2(acc[p], pack2(kv.x, kv.y), q2);
                    }
                }
                float sc[6];
#pragma unroll
                for (int p = 0; p < 3; p++) {
                    float2 v = unpack2(acc[p]);
                    float2 bb = *reinterpret_cast<const float2*>(&s.bias[t0 + 2 * p]);
                    sc[2 * p] = v.x * scale + bb.x;
                    sc[2 * p + 1] = v.y * scale + bb.y;
                }
                float m = sc[0];
#pragma unroll
                for (int e = 1; e < 6; e++) m = fmaxf(m, sc[e]);
#pragma unroll
                for (int o = 1; o < 8; o <<= 1) m = fmaxf(m, __shfl_xor_sync(0xffffffffu, m, o, 8));
                float sum = 0.f;
#pragma unroll
                for (int e = 0; e < 6; e++) { sc[e] = __expf(sc[e] - m); sum += sc[e]; }
#pragma unroll
                for (int o = 1; o < 8; o <<= 1) sum += __shfl_xor_sync(0xffffffffu, sum, o, 8);
                float inv = 1.f / sum;
#pragma unroll
                for (int p = 0; p < 3; p++)
                    *reinterpret_cast<float2*>(&s.u.a.sc[r][t0 + 2 * p]) =
                        make_float2(sc[2 * p] * inv, sc[2 * p + 1] * inv);
            }
            __syncthreads();
            // ---- o = a @ V: thread = (colpair p=tid&31, g2=tid>>5: g=g2&3, th=g2>>2) ----
            {
                int p = tid & 31, g2 = tid >> 5;
                int gg = g2 & 3, th = g2 >> 2;
                int r = (p >> 2) * 4 + gg;   // h = p>>2
                ull acc = 0ull;
                const float* arow = s.u.a.sc[r];
#pragma unroll
                for (int t = th * 24; t < th * 24 + 24; t++) {
                    float av = arow[t];
                    float2 vv = *reinterpret_cast<const float2*>(&s.V[t][2 * p]);
                    fma2(acc, pack2(vv.x, vv.y), pack2(av, av));
                }
                *reinterpret_cast<float2*>(&s.u.a.o2[th][gg][2 * p]) = unpack2(acc);
            }
            __syncthreads();
            s.u.a.o[g][c] = s.u.a.o2[0][g][c] + s.u.a.o2[1][g][c];
            __syncthreads();
            // ---- H += o @ Wo ----
            {
                float acc = 0.f;
#pragma unroll
                for (int kc = 0; kc < 64; kc += 16) {
                    float w[16];
#pragma unroll
                    for (int j = 0; j < 16; j++) w[j] = P.Wo[woff + (kc + j) * 64 + c];
                    const float4* o4 = reinterpret_cast<const float4*>(&s.u.a.o[g][kc]);
#pragma unroll
                    for (int q4 = 0; q4 < 4; q4++) {
                        float4 ov = o4[q4];
                        acc += ov.x * w[4 * q4] + ov.y * w[4 * q4 + 1] + ov.z * w[4 * q4 + 2] + ov.w * w[4 * q4 + 3];
                    }
                }
                s.H[g][c] += acc;
            }
            __syncthreads();
        }

        // ---- cross attention ----
        {
            float acc1 = 0.f, acc2 = 0.f;
#pragma unroll
            for (int kc = 0; kc < 64; kc += 8) {
                float wk[8], wv[8];
#pragma unroll
                for (int j = 0; j < 8; j++) {
                    wk[j] = P.Wk2[str * 4096 + (kc + j) * 64 + c];
                    wv[j] = P.Wv2[str * 4096 + (kc + j) * 64 + c];
                }
#pragma unroll
                for (int j = 0; j < 8; j++) {
                    float hv = s.H[g][kc + j];
                    acc1 += hv * wk[j];
                    acc2 += hv * wv[j];
                }
            }
            s.u.a.k2[g][c] = acc1;
            s.u.a.v2[g][c] = acc2;
            if (tid < 32) {
                int p = tid, j = p & 3;
                float r0 = 0.f, r1 = 0.f;
#pragma unroll
                for (int k = 0; k < 64; k++) {
                    float qv = ctxT[k * TSTR + 48];
                    r0 += qv * P.Wq2[str * 4096 + k * 64 + 2 * p];
                    r1 += qv * P.Wq2[str * 4096 + k * 64 + 2 * p + 1];
                }
                float cc = s.cs[48][j], sn = s.sn[48][j];
                s.u.a.qc[2 * p]     = cc * r0 - sn * r1;
                s.u.a.qc[2 * p + 1] = sn * r0 + cc * r1;
            }
        }
        __syncthreads();
        if (tid < 8) {
            int h = tid;
            float scv[4], m = -1e30f;
#pragma unroll
            for (int i = 0; i < 4; i++) {
                float acc = 0.f;
#pragma unroll
                for (int dd = 0; dd < 8; dd++) acc += s.u.a.qc[h * 8 + dd] * s.u.a.k2[i][h * 8 + dd];
                scv[i] = acc * scale;
                m = fmaxf(m, scv[i]);
            }
            float sum = 0.f;
#pragma unroll
            for (int i = 0; i < 4; i++) { scv[i] = __expf(scv[i] - m); sum += scv[i]; }
            float inv = 1.f / sum;
#pragma unroll
            for (int i = 0; i < 4; i++) s.u.a.a2[h * 4 + i] = scv[i] * inv;
        }
        __syncthreads();
        if (tid < 64) {
            int h = tid >> 3;
            float acc = 0.f;
#pragma unroll
            for (int i = 0; i < 4; i++) acc += s.u.a.a2[h * 4 + i] * s.u.a.v2[i][tid];
            s.u.a.outv[tid] = acc;
        }
        __syncthreads();
        if (tid < 64) {
            float acc = 0.f;
#pragma unroll
            for (int k = 0; k < 64; k++) acc += s.u.a.outv[k] * P.Wo2[str * 4096 + k * 64 + tid];
            enc[(size_t)b * DEC_IN + str * 64 + tid] = acc;
        }
        __syncthreads();
    }

    if (tid < 10) enc[(size_t)b * DEC_IN + 128 + tid] = s.in[48][tid];
}

// ---------------- decoder GEMMs ----------------
template <bool ACT>
__global__ void __launch_bounds__(256) gemm_kernel(const float* __restrict__ A, const float* __restrict__ B,
                                                   const float* __restrict__ bias, float* __restrict__ C,
                                                   int M, int N, int K) {
    const int BK = 16;
    __shared__ float As[BK][68];
    __shared__ float Bs[BK][64];
    int tx = threadIdx.x & 15, ty = threadIdx.x >> 4;
    int bm = blockIdx.x * 64, bn = blockIdx.y * 64;
    float acc[4][4] = {};
    for (int k0 = 0; k0 < K; k0 += BK) {
        for (int idx = threadIdx.x; idx < 64 * BK; idx += 256) {
            int r = idx >> 4, kk = idx & 15;
            As[kk][r] = (k0 + kk < K) ? A[(size_t)(bm + r) * K + k0 + kk] : 0.f;
        }
        for (int idx = threadIdx.x; idx < BK * 64; idx += 256) {
            int kk = idx >> 6, cc = idx & 63;
            Bs[kk][cc] = (k0 + kk < K) ? B[(size_t)(k0 + kk) * N + bn + cc] : 0.f;
        }
        __syncthreads();
#pragma unroll
        for (int kk = 0; kk < BK; kk++) {
            float4 av = *(const float4*)&As[kk][ty * 4];
            float4 bv = *(const float4*)&Bs[kk][tx * 4];
            float a[4] = {av.x, av.y, av.z, av.w};
            float bb[4] = {bv.x, bv.y, bv.z, bv.w};
#pragma unroll
            for (int i = 0; i < 4; i++)
#pragma unroll
                for (int j = 0; j < 4; j++) acc[i][j] += a[i] * bb[j];
        }
        __syncthreads();
    }
#pragma unroll
    for (int i = 0; i < 4; i++) {
        int r = bm + ty * 4 + i;
#pragma unroll
        for (int j = 0; j < 4; j++) {
            int cc = bn + tx * 4 + j;
            float v = acc[i][j] + bias[cc];
            if (ACT) v -= tanhf(v);
            C[(size_t)r * N + cc] = v;
        }
    }
}

__global__ void __launch_bounds__(256) final_gemv(const float* __restrict__ H1, const float* __restrict__ w,
                                                  const float* __restrict__ b2, float* __restrict__ out) {
    int b = blockIdx.x * 8 + (threadIdx.x >> 5);
    int lane = threadIdx.x & 31;
    const float* row = H1 + (size_t)b * 256;
    float acc = 0.f;
#pragma unroll
    for (int k = lane; k < 256; k += 32) acc += row[k] * w[k];
#pragma unroll
    for (int o = 16; o; o >>= 1) acc += __shfl_down_sync(0xffffffffu, acc, o);
    if (lane == 0) out[b] = acc + b2[0];
}

// ---------------- launch ----------------
extern "C" void kernel_launch(void* const* d_in, const int* in_sizes, int n_in,
                              void* d_out, int out_size) {
    const float* in_t = (const float*)d_in[0];
    MainParams P;
    P.in = in_t;
    P.dists = (const float*)d_in[1];
    P.gamma = (const float*)d_in[3];  P.beta = (const float*)d_in[4];
    P.xe_w1 = (const float*)d_in[5];  P.xe_b1 = (const float*)d_in[6];
    P.xe_w2 = (const float*)d_in[7];  P.xe_b2 = (const float*)d_in[8];
    P.ye_w1 = (const float*)d_in[9];  P.ye_b1 = (const float*)d_in[10];
    P.ye_w2 = (const float*)d_in[11]; P.ye_b2 = (const float*)d_in[12];
    P.learnable_y = (const float*)d_in[13];
    P.hidden_tokens = (const float*)d_in[14];
    P.Wq = (const float*)d_in[15]; P.Wk = (const float*)d_in[16];
    P.Wv = (const float*)d_in[17]; P.Wo = (const float*)d_in[18];
    P.Wq2 = (const float*)d_in[19]; P.Wk2 = (const float*)d_in[20];
    P.Wv2 = (const float*)d_in[21]; P.Wo2 = (const float*)d_in[22];
    const float* dec_w0 = (const float*)d_in[23];
    const float* dec_b0 = (const float*)d_in[24];
    const float* dec_w1 = (const float*)d_in[25];
    const float* dec_b1 = (const float*)d_in[26];
    const float* dec_w2 = (const float*)d_in[27];
    const float* dec_b2 = (const float*)d_in[28];
    float* out = (float*)d_out;

    float *enc, *h0, *h1;
    cudaGetSymbolAddress((void**)&enc, g_enc);
    cudaGetSymbolAddress((void**)&h0, g_h0);
    cudaGetSymbolAddress((void**)&h1, g_h1);

    cudaFuncSetAttribute((const void*)k_main, cudaFuncAttributeMaxDynamicSharedMemorySize,
                         (int)sizeof(Smem));

    bn_zero_kernel<<<1, 32>>>();
    bn_acc_kernel<<<256, 256>>>(in_t);
    bn_fin_kernel<<<1, 32>>>();
    k_main<<<BSZ, 256, sizeof(Smem)>>>(P, enc);
    gemm_kernel<true><<<dim3(BSZ / 64, 512 / 64), 256>>>(enc, dec_w0, dec_b0, h0, BSZ, 512, DEC_IN);
    gemm_kernel<true><<<dim3(BSZ / 64, 256 / 64), 256>>>(h0, dec_w1, dec_b1, h1, BSZ, 256, 512);
    final_gemv<<<BSZ / 8, 256>>>(h1, dec_w2, dec_b2, out);
}

// round 4
// speedup vs baseline: 1.4535x; 1.0213x over previous
#include <cuda_runtime.h>
#include <math.h>

#define BSZ 8192
#define SLN 49
#define FDIM 11
#define DEC_IN 138

typedef unsigned long long ull;

__device__ __forceinline__ void fma2(ull& d, ull a, ull b) {
    asm("fma.rn.f32x2 %0, %1, %2, %0;" : "+l"(d) : "l"(a), "l"(b));
}
__device__ __forceinline__ ull pack2(float x, float y) {
    ull u; asm("mov.b64 %0, {%1, %2};" : "=l"(u) : "f"(x), "f"(y)); return u;
}
__device__ __forceinline__ float2 unpack2(ull u) {
    float2 v; asm("mov.b64 {%0, %1}, %2;" : "=f"(v.x), "=f"(v.y) : "l"(u)); return v;
}

// ---------------- device scratch ----------------
__device__ float g_sum[9];
__device__ float g_sumsq[9];
__device__ float g_mean[9];
__device__ float g_rstd[9];
__device__ float g_enc[BSZ * DEC_IN];
__device__ float g_h0[BSZ * 512];
__device__ float g_h1[BSZ * 256];

// ---------------- batch-norm statistics ----------------
__global__ void bn_zero_kernel() {
    if (threadIdx.x < 9) { g_sum[threadIdx.x] = 0.f; g_sumsq[threadIdx.x] = 0.f; }
}

__global__ void bn_acc_kernel(const float* __restrict__ in) {
    float ls[9], lq[9];
#pragma unroll
    for (int f = 0; f < 9; f++) { ls[f] = 0.f; lq[f] = 0.f; }
    int idx0 = blockIdx.x * blockDim.x + threadIdx.x;
    for (int r = idx0; r < BSZ * SLN; r += gridDim.x * blockDim.x) {
        const float* p = in + (size_t)r * FDIM;
#pragma unroll
        for (int f = 0; f < 9; f++) {
            float v = p[f < 8 ? f : 10];
            ls[f] += v; lq[f] += v * v;
        }
    }
#pragma unroll
    for (int f = 0; f < 9; f++) {
#pragma unroll
        for (int o = 16; o; o >>= 1) {
            ls[f] += __shfl_down_sync(0xffffffffu, ls[f], o);
            lq[f] += __shfl_down_sync(0xffffffffu, lq[f], o);
        }
    }
    if ((threadIdx.x & 31) == 0) {
#pragma unroll
        for (int f = 0; f < 9; f++) {
            atomicAdd(&g_sum[f], ls[f]);
            atomicAdd(&g_sumsq[f], lq[f]);
        }
    }
}

__global__ void bn_fin_kernel() {
    int f = threadIdx.x;
    if (f < 9) {
        float n = (float)(BSZ * SLN);
        float mu = g_sum[f] / n;
        float var = g_sumsq[f] / n - mu * mu;
        g_mean[f] = mu;
        g_rstd[f] = rsqrtf(var + 1e-5f);
    }
}

// ---------------- main per-element transformer kernel ----------------
struct MainParams {
    const float *in, *dists, *gamma, *beta;
    const float *xe_w1, *xe_b1, *xe_w2, *xe_b2;
    const float *ye_w1, *ye_b1, *ye_w2, *ye_b2;
    const float *learnable_y, *hidden_tokens;
    const float *Wq, *Wk, *Wv, *Wo, *Wq2, *Wk2, *Wv2, *Wo2;
};

#define TSTR 52   // ctxT / tmpT row stride (floats)
#define KSTR 50   // KT row stride
#define SCSTR 50  // sc row stride

struct __align__(16) Smem {
    float in[SLN][12];
    float cs[SLN][4];
    float sn[SLN][4];
    float bias[48];
    float ctxT[64][TSTR];  // transposed ctx embed (x, then recomputed as y)
    float KT[64][KSTR];    // transposed keys
    float V[48][64];
    float H[4][64];
    union {
        float tmpT[64][TSTR];  // embed intermediate
        struct {
            float sc[32][SCSTR];  // attention weights / cross-attn partials
            float q[4][64];
            float o[4][64];
            float o2[2][4][64];
            float k2[4][64];
            float v2[4][64];
            float qc[64];
            float outv[64];
            float a2[32];
        } a;
    } u;
};

// stage2 of an embed: ctxT[c][t] = bias + sum_k tmpT[k][t] * W[k*64+c]
__device__ __forceinline__ void embed_stage2(Smem& s, const float* __restrict__ W,
                                             const float* __restrict__ bvec,
                                             int c, int g, bool tail48) {
    const float b2v = bvec[c];
    const int t0 = g * 12;
    ull acc[6];
#pragma unroll
    for (int p = 0; p < 6; p++) acc[p] = pack2(b2v, b2v);
    const float* Wc = W + c;
    for (int kc = 0; kc < 64; kc += 2) {
        float w0 = Wc[kc * 64];
        float w1 = Wc[(kc + 1) * 64];
#pragma unroll
        for (int jj = 0; jj < 2; jj++) {
            ull w2 = pack2(jj ? w1 : w0, jj ? w1 : w0);
            const ulonglong2* act = reinterpret_cast<const ulonglong2*>(&s.u.tmpT[kc + jj][t0]);
#pragma unroll
            for (int p = 0; p < 3; p++) {
                ulonglong2 a4 = act[p];
                fma2(acc[2 * p], a4.x, w2);
                fma2(acc[2 * p + 1], a4.y, w2);
            }
        }
    }
#pragma unroll
    for (int p = 0; p < 6; p++)
        *reinterpret_cast<float2*>(&s.ctxT[c][t0 + 2 * p]) = unpack2(acc[p]);
    if (tail48 && g == 0) {
        float acc48 = b2v;
        for (int k = 0; k < 64; k++) acc48 += s.u.tmpT[k][48] * W[k * 64 + c];
        s.ctxT[c][48] = acc48;
    }
}

__global__ void __launch_bounds__(256, 4) k_main(MainParams P, float* __restrict__ enc) {
    extern __shared__ char smem_raw[];
    Smem& s = *reinterpret_cast<Smem*>(smem_raw);
    const int tid = threadIdx.x;
    const int b = blockIdx.x;
    const int c = tid & 63;    // column 0..63
    const int g = tid >> 6;    // row-group 0..3

    const float* ib = P.in + (size_t)b * SLN * FDIM;

    // ---- phase 0 ----
    for (int idx = tid; idx < SLN * FDIM; idx += 256) {
        int t = idx / FDIM, cc = idx % FDIM;
        float v = ib[idx];
        if (cc < 8 || cc == 10) {
            int f = (cc < 8) ? cc : 8;
            v = (v - g_mean[f]) * g_rstd[f] * P.gamma[f] + P.beta[f];
        }
        s.in[t][cc] = v;
    }
    for (int idx = tid; idx < 48; idx += 256) s.bias[idx] = -P.dists[(size_t)b * SLN + idx];
    for (int idx = tid; idx < SLN * 4; idx += 256) {
        int t = idx >> 2, j = idx & 3;
        float x = ib[t * FDIM + 8], y = ib[t * FDIM + 9];
        float ang = (j == 0) ? 10.f * x : (j == 1) ? 10.f * y : (j == 2) ? x : y;
        s.cs[t][j] = cosf(ang);
        s.sn[t][j] = sinf(ang);
    }
    __syncthreads();

    // ---- x embed stage1 ----
    {
        float w[8];
#pragma unroll
        for (int k = 0; k < 8; k++) w[k] = P.xe_w1[k * 64 + c];
        float b1 = P.xe_b1[c];
        for (int t = g; t < SLN; t += 4) {
            float acc = b1;
#pragma unroll
            for (int k = 0; k < 8; k++) acc += s.in[t][k] * w[k];
            s.u.tmpT[c][t] = acc - tanhf(acc);
        }
    }
    __syncthreads();
    embed_stage2(s, P.xe_w2, P.xe_b2, c, g, true);
    __syncthreads();

    const float scale = 0.35355339059327373f;  // 1/sqrt(8)

#pragma unroll 1
    for (int str = 0; str < 2; ++str) {
        if (str == 1) {
            // recompute ctx as y-embed (stream0 fully done with ctxT)
            {
                float w1 = P.ye_w1[c], b1 = P.ye_b1[c];
                for (int t = g; t < 48; t += 4) {
                    float acc = s.in[t][10] * w1 + b1;
                    s.u.tmpT[c][t] = acc - tanhf(acc);
                }
            }
            __syncthreads();
            embed_stage2(s, P.ye_w2, P.ye_b2, c, g, false);
            if (g == 0) s.ctxT[c][48] = P.learnable_y[c];
            __syncthreads();
        }
        const float* ctxT = &s.ctxT[0][0];
        s.H[g][c] = P.hidden_tokens[g * 64 + c];
        __syncthreads();

#pragma unroll 1
        for (int l = 0; l < 2; ++l) {
            const int woff = (l * 2 + str) * 4096;
            // ---- merged K+V projection (K transposed) ----
            {
                const int t0 = g * 12;
                ull accK[6], accV[6];
#pragma unroll
                for (int p = 0; p < 6; p++) { accK[p] = 0ull; accV[p] = 0ull; }
                const float* WkB = P.Wk + woff + c;
                const float* WvB = P.Wv + woff + c;
                for (int kc = 0; kc < 64; kc += 2) {
                    float wk0 = WkB[kc * 64], wk1 = WkB[(kc + 1) * 64];
                    float wv0 = WvB[kc * 64], wv1 = WvB[(kc + 1) * 64];
#pragma unroll
                    for (int jj = 0; jj < 2; jj++) {
                        ull wk2 = pack2(jj ? wk1 : wk0, jj ? wk1 : wk0);
                        ull wv2 = pack2(jj ? wv1 : wv0, jj ? wv1 : wv0);
                        const ulonglong2* act = reinterpret_cast<const ulonglong2*>(&ctxT[(kc + jj) * TSTR + t0]);
#pragma unroll
                        for (int p = 0; p < 3; p++) {
                            ulonglong2 a4 = act[p];
                            fma2(accK[2 * p], a4.x, wk2);
                            fma2(accK[2 * p + 1], a4.y, wk2);
                            fma2(accV[2 * p], a4.x, wv2);
                            fma2(accV[2 * p + 1], a4.y, wv2);
                        }
                    }
                }
#pragma unroll
                for (int p = 0; p < 6; p++)
                    *reinterpret_cast<float2*>(&s.KT[c][t0 + 2 * p]) = unpack2(accK[p]);
#pragma unroll
                for (int p = 0; p < 6; p++) {
                    float2 vv = unpack2(accV[p]);
                    s.V[t0 + 2 * p][c] = vv.x;
                    s.V[t0 + 2 * p + 1][c] = vv.y;
                }
            }
            // ---- q projection ----
            {
                float acc = 0.f;
#pragma unroll
                for (int kc = 0; kc < 64; kc += 8) {
                    float w[8];
#pragma unroll
                    for (int j = 0; j < 8; j++) w[j] = P.Wq[woff + (kc + j) * 64 + c];
                    const float4* h4 = reinterpret_cast<const float4*>(&s.H[g][kc]);
#pragma unroll
                    for (int q4 = 0; q4 < 2; q4++) {
                        float4 hv = h4[q4];
                        acc += hv.x * w[4 * q4] + hv.y * w[4 * q4 + 1] + hv.z * w[4 * q4 + 2] + hv.w * w[4 * q4 + 3];
                    }
                }
                s.u.a.q[g][c] = acc;
            }
            __syncthreads();
            // ---- rope on KT ----
            {
                int p = tid >> 3, tg = tid & 7, j = p & 3;
                int t0 = tg * 6;
                float2 e0[3], e1[3];
#pragma unroll
                for (int q2 = 0; q2 < 3; q2++) {
                    e0[q2] = *reinterpret_cast<float2*>(&s.KT[2 * p][t0 + 2 * q2]);
                    e1[q2] = *reinterpret_cast<float2*>(&s.KT[2 * p + 1][t0 + 2 * q2]);
                }
#pragma unroll
                for (int q2 = 0; q2 < 3; q2++) {
#pragma unroll
                    for (int e = 0; e < 2; e++) {
                        int t = t0 + 2 * q2 + e;
                        float cc = s.cs[t][j], sn = s.sn[t][j];
                        float a0 = (e == 0) ? e0[q2].x : e0[q2].y;
                        float a1 = (e == 0) ? e1[q2].x : e1[q2].y;
                        float r0 = cc * a0 - sn * a1;
                        float r1 = sn * a0 + cc * a1;
                        if (e == 0) { e0[q2].x = r0; e1[q2].x = r1; }
                        else        { e0[q2].y = r0; e1[q2].y = r1; }
                    }
                }
#pragma unroll
                for (int q2 = 0; q2 < 3; q2++) {
                    *reinterpret_cast<float2*>(&s.KT[2 * p][t0 + 2 * q2]) = e0[q2];
                    *reinterpret_cast<float2*>(&s.KT[2 * p + 1][t0 + 2 * q2]) = e1[q2];
                }
            }
            __syncthreads();
            // ---- fused scores + softmax ----
            {
                int r = tid >> 3, l8 = tid & 7;
                int h = r >> 2, i = r & 3;
                int t0 = l8 * 6;
                ull acc[3] = {0ull, 0ull, 0ull};
#pragma unroll
                for (int d = 0; d < 8; d++) {
                    float qv = s.u.a.q[i][h * 8 + d];
                    ull q2 = pack2(qv, qv);
                    const float2* kt = reinterpret_cast<const float2*>(&s.KT[h * 8 + d][t0]);
#pragma unroll
                    for (int p = 0; p < 3; p++) {
                        float2 kv = kt[p];
                        fma2(acc[p], pack2(kv.x, kv.y), q2);
                    }
                }
                float sc[6];
#pragma unroll
                for (int p = 0; p < 3; p++) {
                    float2 v = unpack2(acc[p]);
                    float2 bb = *reinterpret_cast<const float2*>(&s.bias[t0 + 2 * p]);
                    sc[2 * p] = v.x * scale + bb.x;
                    sc[2 * p + 1] = v.y * scale + bb.y;
                }
                float m = sc[0];
#pragma unroll
                for (int e = 1; e < 6; e++) m = fmaxf(m, sc[e]);
#pragma unroll
                for (int o = 1; o < 8; o <<= 1) m = fmaxf(m, __shfl_xor_sync(0xffffffffu, m, o, 8));
                float sum = 0.f;
#pragma unroll
                for (int e = 0; e < 6; e++) { sc[e] = __expf(sc[e] - m); sum += sc[e]; }
#pragma unroll
                for (int o = 1; o < 8; o <<= 1) sum += __shfl_xor_sync(0xffffffffu, sum, o, 8);
                float inv = 1.f / sum;
#pragma unroll
                for (int p = 0; p < 3; p++)
                    *reinterpret_cast<float2*>(&s.u.a.sc[r][t0 + 2 * p]) =
                        make_float2(sc[2 * p] * inv, sc[2 * p + 1] * inv);
            }
            __syncthreads();
            // ---- o = a @ V ----
            {
                int p = tid & 31, g2 = tid >> 5;
                int gg = g2 & 3, th = g2 >> 2;
                int r = (p >> 2) * 4 + gg;
                ull acc = 0ull;
                const float* arow = s.u.a.sc[r];
#pragma unroll
                for (int t = th * 24; t < th * 24 + 24; t++) {
                    float av = arow[t];
                    float2 vv = *reinterpret_cast<const float2*>(&s.V[t][2 * p]);
                    fma2(acc, pack2(vv.x, vv.y), pack2(av, av));
                }
                *reinterpret_cast<float2*>(&s.u.a.o2[th][gg][2 * p]) = unpack2(acc);
            }
            __syncthreads();
            s.u.a.o[g][c] = s.u.a.o2[0][g][c] + s.u.a.o2[1][g][c];
            __syncthreads();
            // ---- H += o @ Wo ----
            {
                float acc = 0.f;
#pragma unroll
                for (int kc = 0; kc < 64; kc += 8) {
                    float w[8];
#pragma unroll
                    for (int j = 0; j < 8; j++) w[j] = P.Wo[woff + (kc + j) * 64 + c];
                    const float4* o4 = reinterpret_cast<const float4*>(&s.u.a.o[g][kc]);
#pragma unroll
                    for (int q4 = 0; q4 < 2; q4++) {
                        float4 ov = o4[q4];
                        acc += ov.x * w[4 * q4] + ov.y * w[4 * q4 + 1] + ov.z * w[4 * q4 + 2] + ov.w * w[4 * q4 + 3];
                    }
                }
                s.H[g][c] += acc;
            }
            __syncthreads();
        }

        // ---- cross attention: k-split projections (weight redundancy 4x -> 1x) ----
        {
            const float* Wk2B = P.Wk2 + str * 4096 + c;
            const float* Wv2B = P.Wv2 + str * 4096 + c;
            float pk[4] = {0.f, 0.f, 0.f, 0.f}, pv[4] = {0.f, 0.f, 0.f, 0.f};
            const int k0 = g * 16;
            for (int kk = k0; kk < k0 + 16; kk += 2) {
                float wkA = Wk2B[kk * 64], wkB_ = Wk2B[(kk + 1) * 64];
                float wvA = Wv2B[kk * 64], wvB_ = Wv2B[(kk + 1) * 64];
#pragma unroll
                for (int i = 0; i < 4; i++) {
                    float2 hv = *reinterpret_cast<const float2*>(&s.H[i][kk]);
                    pk[i] += hv.x * wkA + hv.y * wkB_;
                    pv[i] += hv.x * wvA + hv.y * wvB_;
                }
            }
            float* part = &s.u.a.sc[0][0];
#pragma unroll
            for (int i = 0; i < 4; i++) {
                part[g * 256 + i * 64 + c] = pk[i];
                part[1024 + g * 256 + i * 64 + c] = pv[i];
            }
        }
        __syncthreads();
        {
            const float* part = &s.u.a.sc[0][0];
            float k2v = part[g * 64 + c] + part[256 + g * 64 + c] + part[512 + g * 64 + c] + part[768 + g * 64 + c];
            float v2v = part[1024 + g * 64 + c] + part[1280 + g * 64 + c] + part[1536 + g * 64 + c] + part[1792 + g * 64 + c];
            s.u.a.k2[g][c] = k2v;
            s.u.a.v2[g][c] = v2v;
            if (tid < 32) {
                int p = tid, j = p & 3;
                float r0 = 0.f, r1 = 0.f;
#pragma unroll
                for (int k = 0; k < 64; k++) {
                    float qv = s.ctxT[k][48];
                    r0 += qv * P.Wq2[str * 4096 + k * 64 + 2 * p];
                    r1 += qv * P.Wq2[str * 4096 + k * 64 + 2 * p + 1];
                }
                float cc = s.cs[48][j], sn = s.sn[48][j];
                s.u.a.qc[2 * p]     = cc * r0 - sn * r1;
                s.u.a.qc[2 * p + 1] = sn * r0 + cc * r1;
            }
        }
        __syncthreads();
        if (tid < 8) {
            int h = tid;
            float scv[4], m = -1e30f;
#pragma unroll
            for (int i = 0; i < 4; i++) {
                float acc = 0.f;
#pragma unroll
                for (int dd = 0; dd < 8; dd++) acc += s.u.a.qc[h * 8 + dd] * s.u.a.k2[i][h * 8 + dd];
                scv[i] = acc * scale;
                m = fmaxf(m, scv[i]);
            }
            float sum = 0.f;
#pragma unroll
            for (int i = 0; i < 4; i++) { scv[i] = __expf(scv[i] - m); sum += scv[i]; }
            float inv = 1.f / sum;
#pragma unroll
            for (int i = 0; i < 4; i++) s.u.a.a2[h * 4 + i] = scv[i] * inv;
        }
        __syncthreads();
        if (tid < 64) {
            int h = tid >> 3;
            float acc = 0.f;
#pragma unroll
            for (int i = 0; i < 4; i++) acc += s.u.a.a2[h * 4 + i] * s.u.a.v2[i][tid];
            s.u.a.outv[tid] = acc;
        }
        __syncthreads();
        if (tid < 64) {
            float acc = 0.f;
#pragma unroll
            for (int k = 0; k < 64; k++) acc += s.u.a.outv[k] * P.Wo2[str * 4096 + k * 64 + tid];
            enc[(size_t)b * DEC_IN + str * 64 + tid] = acc;
        }
        __syncthreads();
    }

    if (tid < 10) enc[(size_t)b * DEC_IN + 128 + tid] = s.in[48][tid];
}

// ---------------- decoder GEMMs ----------------
template <bool ACT>
__global__ void __launch_bounds__(256) gemm_kernel(const float* __restrict__ A, const float* __restrict__ B,
                                                   const float* __restrict__ bias, float* __restrict__ C,
                                                   int M, int N, int K) {
    const int BK = 16;
    __shared__ float As[BK][68];
    __shared__ float Bs[BK][64];
    int tx = threadIdx.x & 15, ty = threadIdx.x >> 4;
    int bm = blockIdx.x * 64, bn = blockIdx.y * 64;
    float acc[4][4] = {};
    for (int k0 = 0; k0 < K; k0 += BK) {
        for (int idx = threadIdx.x; idx < 64 * BK; idx += 256) {
            int r = idx >> 4, kk = idx & 15;
            As[kk][r] = (k0 + kk < K) ? A[(size_t)(bm + r) * K + k0 + kk] : 0.f;
        }
        for (int idx = threadIdx.x; idx < BK * 64; idx += 256) {
            int kk = idx >> 6, cc = idx & 63;
            Bs[kk][cc] = (k0 + kk < K) ? B[(size_t)(k0 + kk) * N + bn + cc] : 0.f;
        }
        __syncthreads();
#pragma unroll
        for (int kk = 0; kk < BK; kk++) {
            float4 av = *(const float4*)&As[kk][ty * 4];
            float4 bv = *(const float4*)&Bs[kk][tx * 4];
            float a[4] = {av.x, av.y, av.z, av.w};
            float bb[4] = {bv.x, bv.y, bv.z, bv.w};
#pragma unroll
            for (int i = 0; i < 4; i++)
#pragma unroll
                for (int j = 0; j < 4; j++) acc[i][j] += a[i] * bb[j];
        }
        __syncthreads();
    }
#pragma unroll
    for (int i = 0; i < 4; i++) {
        int r = bm + ty * 4 + i;
#pragma unroll
        for (int j = 0; j < 4; j++) {
            int cc = bn + tx * 4 + j;
            float v = acc[i][j] + bias[cc];
            if (ACT) v -= tanhf(v);
            C[(size_t)r * N + cc] = v;
        }
    }
}

__global__ void __launch_bounds__(256) final_gemv(const float* __restrict__ H1, const float* __restrict__ w,
                                                  const float* __restrict__ b2, float* __restrict__ out) {
    int b = blockIdx.x * 8 + (threadIdx.x >> 5);
    int lane = threadIdx.x & 31;
    const float* row = H1 + (size_t)b * 256;
    float acc = 0.f;
#pragma unroll
    for (int k = lane; k < 256; k += 32) acc += row[k] * w[k];
#pragma unroll
    for (int o = 16; o; o >>= 1) acc += __shfl_down_sync(0xffffffffu, acc, o);
    if (lane == 0) out[b] = acc + b2[0];
}

// ---------------- launch ----------------
extern "C" void kernel_launch(void* const* d_in, const int* in_sizes, int n_in,
                              void* d_out, int out_size) {
    const float* in_t = (const float*)d_in[0];
    MainParams P;
    P.in = in_t;
    P.dists = (const float*)d_in[1];
    P.gamma = (const float*)d_in[3];  P.beta = (const float*)d_in[4];
    P.xe_w1 = (const float*)d_in[5];  P.xe_b1 = (const float*)d_in[6];
    P.xe_w2 = (const float*)d_in[7];  P.xe_b2 = (const float*)d_in[8];
    P.ye_w1 = (const float*)d_in[9];  P.ye_b1 = (const float*)d_in[10];
    P.ye_w2 = (const float*)d_in[11]; P.ye_b2 = (const float*)d_in[12];
    P.learnable_y = (const float*)d_in[13];
    P.hidden_tokens = (const float*)d_in[14];
    P.Wq = (const float*)d_in[15]; P.Wk = (const float*)d_in[16];
    P.Wv = (const float*)d_in[17]; P.Wo = (const float*)d_in[18];
    P.Wq2 = (const float*)d_in[19]; P.Wk2 = (const float*)d_in[20];
    P.Wv2 = (const float*)d_in[21]; P.Wo2 = (const float*)d_in[22];
    const float* dec_w0 = (const float*)d_in[23];
    const float* dec_b0 = (const float*)d_in[24];
    const float* dec_w1 = (const float*)d_in[25];
    const float* dec_b1 = (const float*)d_in[26];
    const float* dec_w2 = (const float*)d_in[27];
    const float* dec_b2 = (const float*)d_in[28];
    float* out = (float*)d_out;

    float *enc, *h0, *h1;
    cudaGetSymbolAddress((void**)&enc, g_enc);
    cudaGetSymbolAddress((void**)&h0, g_h0);
    cudaGetSymbolAddress((void**)&h1, g_h1);

    cudaFuncSetAttribute((const void*)k_main, cudaFuncAttributeMaxDynamicSharedMemorySize,
                         (int)sizeof(Smem));

    bn_zero_kernel<<<1, 32>>>();
    bn_acc_kernel<<<256, 256>>>(in_t);
    bn_fin_kernel<<<1, 32>>>();
    k_main<<<BSZ, 256, sizeof(Smem)>>>(P, enc);
    gemm_kernel<true><<<dim3(BSZ / 64, 512 / 64), 256>>>(enc, dec_w0, dec_b0, h0, BSZ, 512, DEC_IN);
    gemm_kernel<true><<<dim3(BSZ / 64, 256 / 64), 256>>>(h0, dec_w1, dec_b1, h1, BSZ, 256, 512);
    final_gemv<<<BSZ / 8, 256>>>(h1, dec_w2, dec_b2, out);
}

// round 5
// speedup vs baseline: 1.5660x; 1.0774x over previous
#include <cuda_runtime.h>
#include <math.h>

#define BSZ 8192
#define SLN 49
#define FDIM 11
#define DEC_IN 138

typedef unsigned long long ull;

__device__ __forceinline__ void fma2(ull& d, ull a, ull b) {
    asm("fma.rn.f32x2 %0, %1, %2, %0;" : "+l"(d) : "l"(a), "l"(b));
}
__device__ __forceinline__ ull pack2(float x, float y) {
    ull u; asm("mov.b64 %0, {%1, %2};" : "=l"(u) : "f"(x), "f"(y)); return u;
}
__device__ __forceinline__ float2 unpack2(ull u) {
    float2 v; asm("mov.b64 {%0, %1}, %2;" : "=f"(v.x), "=f"(v.y) : "l"(u)); return v;
}

// ---------------- device scratch ----------------
__device__ float g_sum[9];
__device__ float g_sumsq[9];
__device__ float g_mean[9];
__device__ float g_rstd[9];
__device__ float g_enc[BSZ * DEC_IN];
__device__ float g_h0[BSZ * 512];
__device__ float g_h1[BSZ * 256];

// ---------------- batch-norm statistics ----------------
__global__ void bn_zero_kernel() {
    if (threadIdx.x < 9) { g_sum[threadIdx.x] = 0.f; g_sumsq[threadIdx.x] = 0.f; }
}

__global__ void bn_acc_kernel(const float* __restrict__ in) {
    float ls[9], lq[9];
#pragma unroll
    for (int f = 0; f < 9; f++) { ls[f] = 0.f; lq[f] = 0.f; }
    int idx0 = blockIdx.x * blockDim.x + threadIdx.x;
    for (int r = idx0; r < BSZ * SLN; r += gridDim.x * blockDim.x) {
        const float* p = in + (size_t)r * FDIM;
#pragma unroll
        for (int f = 0; f < 9; f++) {
            float v = p[f < 8 ? f : 10];
            ls[f] += v; lq[f] += v * v;
        }
    }
#pragma unroll
    for (int f = 0; f < 9; f++) {
#pragma unroll
        for (int o = 16; o; o >>= 1) {
            ls[f] += __shfl_down_sync(0xffffffffu, ls[f], o);
            lq[f] += __shfl_down_sync(0xffffffffu, lq[f], o);
        }
    }
    if ((threadIdx.x & 31) == 0) {
#pragma unroll
        for (int f = 0; f < 9; f++) {
            atomicAdd(&g_sum[f], ls[f]);
            atomicAdd(&g_sumsq[f], lq[f]);
        }
    }
}

__global__ void bn_fin_kernel() {
    int f = threadIdx.x;
    if (f < 9) {
        float n = (float)(BSZ * SLN);
        float mu = g_sum[f] / n;
        float var = g_sumsq[f] / n - mu * mu;
        g_mean[f] = mu;
        g_rstd[f] = rsqrtf(var + 1e-5f);
    }
}

// ---------------- main per-element transformer kernel ----------------
struct MainParams {
    const float *in, *dists, *gamma, *beta;
    const float *xe_w1, *xe_b1, *xe_w2, *xe_b2;
    const float *ye_w1, *ye_b1, *ye_w2, *ye_b2;
    const float *learnable_y, *hidden_tokens;
    const float *Wq, *Wk, *Wv, *Wo, *Wq2, *Wk2, *Wv2, *Wo2;
};

#define TSTR 52   // ctxT / tmpT row stride (floats)
#define KSTR 50   // KT row stride
#define SCSTR 52  // sc row stride (16B-aligned rows for float4)

struct __align__(16) PerElem {
    float in[SLN][12];
    float cs[SLN][4];
    float sn[SLN][4];
    float bias[48];
    float ctxT[64][TSTR];
    float KT[64][KSTR];
    float V[48][64];
    float H[4][64];
    union {
        float tmpT[64][TSTR];
        struct {
            float sc[32][SCSTR];
            float q[4][64];
            float o[4][64];
            float o2[2][4][64];
            float k2[4][64];
            float v2[4][64];
            float qc[64];
            float outv[64];
            float a2[32];
        } a;
    } u;
};

struct __align__(16) Smem { PerElem el[2]; };

__global__ void __launch_bounds__(256, 2) k_main(MainParams P, float* __restrict__ enc) {
    extern __shared__ char smem_raw[];
    Smem& s = *reinterpret_cast<Smem*>(smem_raw);
    const int tid = threadIdx.x;
    const int b = blockIdx.x;          // handles elements 2b, 2b+1
    const int c = tid & 63;
    const int g = tid >> 6;

    // ---- phase 0 ----
#pragma unroll 1
    for (int e = 0; e < 2; e++) {
        PerElem& E = s.el[e];
        const float* ib = P.in + (size_t)(2 * b + e) * SLN * FDIM;
        for (int idx = tid; idx < SLN * FDIM; idx += 256) {
            int t = idx / FDIM, cc = idx % FDIM;
            float v = ib[idx];
            if (cc < 8 || cc == 10) {
                int f = (cc < 8) ? cc : 8;
                v = (v - g_mean[f]) * g_rstd[f] * P.gamma[f] + P.beta[f];
            }
            E.in[t][cc] = v;
        }
        for (int idx = tid; idx < 48; idx += 256)
            E.bias[idx] = -P.dists[(size_t)(2 * b + e) * SLN + idx];
        for (int idx = tid; idx < SLN * 4; idx += 256) {
            int t = idx >> 2, j = idx & 3;
            float x = ib[t * FDIM + 8], y = ib[t * FDIM + 9];
            float ang = (j == 0) ? 10.f * x : (j == 1) ? 10.f * y : (j == 2) ? x : y;
            E.cs[t][j] = cosf(ang);
            E.sn[t][j] = sinf(ang);
        }
    }
    __syncthreads();

    // ---- x embed stage1 ----
    {
        float w[8];
#pragma unroll
        for (int k = 0; k < 8; k++) w[k] = P.xe_w1[k * 64 + c];
        float b1 = P.xe_b1[c];
#pragma unroll
        for (int e = 0; e < 2; e++) {
            PerElem& E = s.el[e];
            for (int t = g; t < SLN; t += 4) {
                float acc = b1;
#pragma unroll
                for (int k = 0; k < 8; k++) acc += E.in[t][k] * w[k];
                E.u.tmpT[c][t] = acc - tanhf(acc);
            }
        }
    }
    __syncthreads();
    // ---- x embed stage2 (both elements share weight loads) ----
    {
        const float b2v = P.xe_b2[c];
        const int t0 = g * 12;
        ull acc[2][6];
#pragma unroll
        for (int e = 0; e < 2; e++)
#pragma unroll
            for (int p = 0; p < 6; p++) acc[e][p] = pack2(b2v, b2v);
        const float* Wc = P.xe_w2 + c;
        for (int kc = 0; kc < 64; kc += 2) {
            float w0 = Wc[kc * 64], w1 = Wc[(kc + 1) * 64];
#pragma unroll
            for (int jj = 0; jj < 2; jj++) {
                ull w2 = pack2(jj ? w1 : w0, jj ? w1 : w0);
#pragma unroll
                for (int e = 0; e < 2; e++) {
                    const ulonglong2* act = reinterpret_cast<const ulonglong2*>(&s.el[e].u.tmpT[kc + jj][t0]);
#pragma unroll
                    for (int p = 0; p < 3; p++) {
                        ulonglong2 a4 = act[p];
                        fma2(acc[e][2 * p], a4.x, w2);
                        fma2(acc[e][2 * p + 1], a4.y, w2);
                    }
                }
            }
        }
#pragma unroll
        for (int e = 0; e < 2; e++)
#pragma unroll
            for (int p = 0; p < 6; p++)
                *reinterpret_cast<float2*>(&s.el[e].ctxT[c][t0 + 2 * p]) = unpack2(acc[e][p]);
        if (g == 0) {
#pragma unroll 1
            for (int e = 0; e < 2; e++) {
                float acc48 = b2v;
                for (int k = 0; k < 64; k++) acc48 += s.el[e].u.tmpT[k][48] * P.xe_w2[k * 64 + c];
                s.el[e].ctxT[c][48] = acc48;
            }
        }
    }
    __syncthreads();

    const float scale = 0.35355339059327373f;  // 1/sqrt(8)

#pragma unroll 1
    for (int str = 0; str < 2; ++str) {
        if (str == 1) {
            // recompute ctx as y-embed
            {
                float w1 = P.ye_w1[c], b1 = P.ye_b1[c];
#pragma unroll
                for (int e = 0; e < 2; e++) {
                    PerElem& E = s.el[e];
                    for (int t = g; t < 48; t += 4) {
                        float acc = E.in[t][10] * w1 + b1;
                        E.u.tmpT[c][t] = acc - tanhf(acc);
                    }
                }
            }
            __syncthreads();
            {
                const float b2v = P.ye_b2[c];
                const int t0 = g * 12;
                ull acc[2][6];
#pragma unroll
                for (int e = 0; e < 2; e++)
#pragma unroll
                    for (int p = 0; p < 6; p++) acc[e][p] = pack2(b2v, b2v);
                const float* Wc = P.ye_w2 + c;
                for (int kc = 0; kc < 64; kc += 2) {
                    float w0 = Wc[kc * 64], w1 = Wc[(kc + 1) * 64];
#pragma unroll
                    for (int jj = 0; jj < 2; jj++) {
                        ull w2 = pack2(jj ? w1 : w0, jj ? w1 : w0);
#pragma unroll
                        for (int e = 0; e < 2; e++) {
                            const ulonglong2* act = reinterpret_cast<const ulonglong2*>(&s.el[e].u.tmpT[kc + jj][t0]);
#pragma unroll
                            for (int p = 0; p < 3; p++) {
                                ulonglong2 a4 = act[p];
                                fma2(acc[e][2 * p], a4.x, w2);
                                fma2(acc[e][2 * p + 1], a4.y, w2);
                            }
                        }
                    }
                }
#pragma unroll
                for (int e = 0; e < 2; e++)
#pragma unroll
                    for (int p = 0; p < 6; p++)
                        *reinterpret_cast<float2*>(&s.el[e].ctxT[c][t0 + 2 * p]) = unpack2(acc[e][p]);
                if (g == 0) {
                    s.el[0].ctxT[c][48] = P.learnable_y[c];
                    s.el[1].ctxT[c][48] = P.learnable_y[c];
                }
            }
            __syncthreads();
        }

#pragma unroll
        for (int e = 0; e < 2; e++) s.el[e].H[g][c] = P.hidden_tokens[g * 64 + c];
        __syncthreads();

#pragma unroll 1
        for (int l = 0; l < 2; ++l) {
            const int woff = (l * 2 + str) * 4096;
            // ---- merged K+V projection, both elements ----
            {
                const int t0 = g * 12;
                ull accK[2][6], accV[2][6];
#pragma unroll
                for (int e = 0; e < 2; e++)
#pragma unroll
                    for (int p = 0; p < 6; p++) { accK[e][p] = 0ull; accV[e][p] = 0ull; }
                const float* WkB = P.Wk + woff + c;
                const float* WvB = P.Wv + woff + c;
                for (int kc = 0; kc < 64; kc += 2) {
                    float wk0 = WkB[kc * 64], wk1 = WkB[(kc + 1) * 64];
                    float wv0 = WvB[kc * 64], wv1 = WvB[(kc + 1) * 64];
#pragma unroll
                    for (int jj = 0; jj < 2; jj++) {
                        ull wk2 = pack2(jj ? wk1 : wk0, jj ? wk1 : wk0);
                        ull wv2 = pack2(jj ? wv1 : wv0, jj ? wv1 : wv0);
#pragma unroll
                        for (int e = 0; e < 2; e++) {
                            const ulonglong2* act = reinterpret_cast<const ulonglong2*>(&s.el[e].ctxT[kc + jj][t0]);
#pragma unroll
                            for (int p = 0; p < 3; p++) {
                                ulonglong2 a4 = act[p];
                                fma2(accK[e][2 * p], a4.x, wk2);
                                fma2(accK[e][2 * p + 1], a4.y, wk2);
                                fma2(accV[e][2 * p], a4.x, wv2);
                                fma2(accV[e][2 * p + 1], a4.y, wv2);
                            }
                        }
                    }
                }
#pragma unroll
                for (int e = 0; e < 2; e++) {
#pragma unroll
                    for (int p = 0; p < 6; p++)
                        *reinterpret_cast<float2*>(&s.el[e].KT[c][t0 + 2 * p]) = unpack2(accK[e][p]);
#pragma unroll
                    for (int p = 0; p < 6; p++) {
                        float2 vv = unpack2(accV[e][p]);
                        s.el[e].V[t0 + 2 * p][c] = vv.x;
                        s.el[e].V[t0 + 2 * p + 1][c] = vv.y;
                    }
                }
            }
            // ---- q projection ----
            {
                float acc[2] = {0.f, 0.f};
#pragma unroll
                for (int kc = 0; kc < 64; kc += 8) {
                    float w[8];
#pragma unroll
                    for (int j = 0; j < 8; j++) w[j] = P.Wq[woff + (kc + j) * 64 + c];
#pragma unroll
                    for (int e = 0; e < 2; e++) {
                        const float4* h4 = reinterpret_cast<const float4*>(&s.el[e].H[g][kc]);
#pragma unroll
                        for (int q4 = 0; q4 < 2; q4++) {
                            float4 hv = h4[q4];
                            acc[e] += hv.x * w[4 * q4] + hv.y * w[4 * q4 + 1] + hv.z * w[4 * q4 + 2] + hv.w * w[4 * q4 + 3];
                        }
                    }
                }
                s.el[0].u.a.q[g][c] = acc[0];
                s.el[1].u.a.q[g][c] = acc[1];
            }
            __syncthreads();
            // ---- rope on KT ----
#pragma unroll 1
            for (int e = 0; e < 2; e++) {
                PerElem& E = s.el[e];
                int p = tid >> 3, tg = tid & 7, j = p & 3;
                int t0 = tg * 6;
                float2 e0[3], e1[3];
#pragma unroll
                for (int q2 = 0; q2 < 3; q2++) {
                    e0[q2] = *reinterpret_cast<float2*>(&E.KT[2 * p][t0 + 2 * q2]);
                    e1[q2] = *reinterpret_cast<float2*>(&E.KT[2 * p + 1][t0 + 2 * q2]);
                }
#pragma unroll
                for (int q2 = 0; q2 < 3; q2++) {
#pragma unroll
                    for (int ee = 0; ee < 2; ee++) {
                        int t = t0 + 2 * q2 + ee;
                        float cc = E.cs[t][j], sn = E.sn[t][j];
                        float a0 = (ee == 0) ? e0[q2].x : e0[q2].y;
                        float a1 = (ee == 0) ? e1[q2].x : e1[q2].y;
                        float r0 = cc * a0 - sn * a1;
                        float r1 = sn * a0 + cc * a1;
                        if (ee == 0) { e0[q2].x = r0; e1[q2].x = r1; }
                        else         { e0[q2].y = r0; e1[q2].y = r1; }
                    }
                }
#pragma unroll
                for (int q2 = 0; q2 < 3; q2++) {
                    *reinterpret_cast<float2*>(&E.KT[2 * p][t0 + 2 * q2]) = e0[q2];
                    *reinterpret_cast<float2*>(&E.KT[2 * p + 1][t0 + 2 * q2]) = e1[q2];
                }
            }
            __syncthreads();
            // ---- fused scores + softmax ----
#pragma unroll 1
            for (int e = 0; e < 2; e++) {
                PerElem& E = s.el[e];
                int r = tid >> 3, l8 = tid & 7;
                int h = r >> 2, i = r & 3;
                int t0 = l8 * 6;
                ull acc[3] = {0ull, 0ull, 0ull};
#pragma unroll
                for (int d = 0; d < 8; d++) {
                    float qv = E.u.a.q[i][h * 8 + d];
                    ull q2 = pack2(qv, qv);
                    const float2* kt = reinterpret_cast<const float2*>(&E.KT[h * 8 + d][t0]);
#pragma unroll
                    for (int p = 0; p < 3; p++) {
                        float2 kv = kt[p];
                        fma2(acc[p], pack2(kv.x, kv.y), q2);
                    }
                }
                float sc[6];
#pragma unroll
                for (int p = 0; p < 3; p++) {
                    float2 v = unpack2(acc[p]);
                    float2 bb = *reinterpret_cast<const float2*>(&E.bias[t0 + 2 * p]);
                    sc[2 * p] = v.x * scale + bb.x;
                    sc[2 * p + 1] = v.y * scale + bb.y;
                }
                float m = sc[0];
#pragma unroll
                for (int ee = 1; ee < 6; ee++) m = fmaxf(m, sc[ee]);
#pragma unroll
                for (int o = 1; o < 8; o <<= 1) m = fmaxf(m, __shfl_xor_sync(0xffffffffu, m, o, 8));
                float sum = 0.f;
#pragma unroll
                for (int ee = 0; ee < 6; ee++) { sc[ee] = __expf(sc[ee] - m); sum += sc[ee]; }
#pragma unroll
                for (int o = 1; o < 8; o <<= 1) sum += __shfl_xor_sync(0xffffffffu, sum, o, 8);
                float inv = 1.f / sum;
#pragma unroll
                for (int p = 0; p < 3; p++)
                    *reinterpret_cast<float2*>(&E.u.a.sc[r][t0 + 2 * p]) =
                        make_float2(sc[2 * p] * inv, sc[2 * p + 1] * inv);
            }
            __syncthreads();
            // ---- o = a @ V (vectorized attention-weight loads) ----
            {
                int p = tid & 31, g2 = tid >> 5;
                int gg = g2 & 3, th = g2 >> 2;
                int r = (p >> 2) * 4 + gg;
#pragma unroll 1
                for (int e = 0; e < 2; e++) {
                    PerElem& E = s.el[e];
                    const float4* ap = reinterpret_cast<const float4*>(&E.u.a.sc[r][th * 24]);
                    ull acc = 0ull;
#pragma unroll
                    for (int q = 0; q < 6; q++) {
                        float4 av = ap[q];
                        float a0[4] = {av.x, av.y, av.z, av.w};
#pragma unroll
                        for (int cmp = 0; cmp < 4; cmp++) {
                            int t = th * 24 + q * 4 + cmp;
                            float2 vv = *reinterpret_cast<const float2*>(&E.V[t][2 * p]);
                            fma2(acc, pack2(vv.x, vv.y), pack2(a0[cmp], a0[cmp]));
                        }
                    }
                    *reinterpret_cast<float2*>(&E.u.a.o2[th][gg][2 * p]) = unpack2(acc);
                }
            }
            __syncthreads();
#pragma unroll
            for (int e = 0; e < 2; e++)
                s.el[e].u.a.o[g][c] = s.el[e].u.a.o2[0][g][c] + s.el[e].u.a.o2[1][g][c];
            __syncthreads();
            // ---- H += o @ Wo ----
            {
                float acc[2] = {0.f, 0.f};
#pragma unroll
                for (int kc = 0; kc < 64; kc += 8) {
                    float w[8];
#pragma unroll
                    for (int j = 0; j < 8; j++) w[j] = P.Wo[woff + (kc + j) * 64 + c];
#pragma unroll
                    for (int e = 0; e < 2; e++) {
                        const float4* o4 = reinterpret_cast<const float4*>(&s.el[e].u.a.o[g][kc]);
#pragma unroll
                        for (int q4 = 0; q4 < 2; q4++) {
                            float4 ov = o4[q4];
                            acc[e] += ov.x * w[4 * q4] + ov.y * w[4 * q4 + 1] + ov.z * w[4 * q4 + 2] + ov.w * w[4 * q4 + 3];
                        }
                    }
                }
                s.el[0].H[g][c] += acc[0];
                s.el[1].H[g][c] += acc[1];
            }
            __syncthreads();
        }

        // ---- cross attention: k-split projections, shared weights ----
        {
            const float* Wk2B = P.Wk2 + str * 4096 + c;
            const float* Wv2B = P.Wv2 + str * 4096 + c;
            float pk[2][4] = {}, pv[2][4] = {};
            const int k0 = g * 16;
            for (int kk = k0; kk < k0 + 16; kk += 2) {
                float wkA = Wk2B[kk * 64], wkB_ = Wk2B[(kk + 1) * 64];
                float wvA = Wv2B[kk * 64], wvB_ = Wv2B[(kk + 1) * 64];
#pragma unroll
                for (int e = 0; e < 2; e++)
#pragma unroll
                    for (int i = 0; i < 4; i++) {
                        float2 hv = *reinterpret_cast<const float2*>(&s.el[e].H[i][kk]);
                        pk[e][i] += hv.x * wkA + hv.y * wkB_;
                        pv[e][i] += hv.x * wvA + hv.y * wvB_;
                    }
            }
#pragma unroll
            for (int e = 0; e < 2; e++) {
                float* part = &s.el[e].u.a.sc[0][0];
#pragma unroll
                for (int i = 0; i < 4; i++) {
                    part[g * 256 + i * 64 + c] = pk[e][i];
                    part[1024 + g * 256 + i * 64 + c] = pv[e][i];
                }
            }
        }
        __syncthreads();
        {
#pragma unroll
            for (int e = 0; e < 2; e++) {
                const float* part = &s.el[e].u.a.sc[0][0];
                float k2v = part[g * 64 + c] + part[256 + g * 64 + c] + part[512 + g * 64 + c] + part[768 + g * 64 + c];
                float v2v = part[1024 + g * 64 + c] + part[1280 + g * 64 + c] + part[1536 + g * 64 + c] + part[1792 + g * 64 + c];
                s.el[e].u.a.k2[g][c] = k2v;
                s.el[e].u.a.v2[g][c] = v2v;
            }
            if (tid < 32) {
                int p = tid, j = p & 3;
                float r0[2] = {0.f, 0.f}, r1[2] = {0.f, 0.f};
                for (int k = 0; k < 64; k++) {
                    float wA = P.Wq2[str * 4096 + k * 64 + 2 * p];
                    float wB = P.Wq2[str * 4096 + k * 64 + 2 * p + 1];
#pragma unroll
                    for (int e = 0; e < 2; e++) {
                        float qv = s.el[e].ctxT[k][48];
                        r0[e] += qv * wA;
                        r1[e] += qv * wB;
                    }
                }
#pragma unroll
                for (int e = 0; e < 2; e++) {
                    float cc = s.el[e].cs[48][j], sn = s.el[e].sn[48][j];
                    s.el[e].u.a.qc[2 * p]     = cc * r0[e] - sn * r1[e];
                    s.el[e].u.a.qc[2 * p + 1] = sn * r0[e] + cc * r1[e];
                }
            }
        }
        __syncthreads();
        if (tid < 8) {
            int h = tid;
#pragma unroll
            for (int e = 0; e < 2; e++) {
                PerElem& E = s.el[e];
                float scv[4], m = -1e30f;
#pragma unroll
                for (int i = 0; i < 4; i++) {
                    float acc = 0.f;
#pragma unroll
                    for (int dd = 0; dd < 8; dd++) acc += E.u.a.qc[h * 8 + dd] * E.u.a.k2[i][h * 8 + dd];
                    scv[i] = acc * scale;
                    m = fmaxf(m, scv[i]);
                }
                float sum = 0.f;
#pragma unroll
                for (int i = 0; i < 4; i++) { scv[i] = __expf(scv[i] - m); sum += scv[i]; }
                float inv = 1.f / sum;
#pragma unroll
                for (int i = 0; i < 4; i++) E.u.a.a2[h * 4 + i] = scv[i] * inv;
            }
        }
        __syncthreads();
        if (tid < 64) {
            int h = tid >> 3;
#pragma unroll
            for (int e = 0; e < 2; e++) {
                PerElem& E = s.el[e];
                float acc = 0.f;
#pragma unroll
                for (int i = 0; i < 4; i++) acc += E.u.a.a2[h * 4 + i] * E.u.a.v2[i][tid];
                E.u.a.outv[tid] = acc;
            }
        }
        __syncthreads();
        if (tid < 64) {
            float acc[2] = {0.f, 0.f};
            for (int k = 0; k < 64; k++) {
                float w = P.Wo2[str * 4096 + k * 64 + tid];
                acc[0] += s.el[0].u.a.outv[k] * w;
                acc[1] += s.el[1].u.a.outv[k] * w;
            }
            enc[(size_t)(2 * b) * DEC_IN + str * 64 + tid] = acc[0];
            enc[(size_t)(2 * b + 1) * DEC_IN + str * 64 + tid] = acc[1];
        }
        __syncthreads();
    }

    if (tid < 10) {
        enc[(size_t)(2 * b) * DEC_IN + 128 + tid] = s.el[0].in[48][tid];
        enc[(size_t)(2 * b + 1) * DEC_IN + 128 + tid] = s.el[1].in[48][tid];
    }
}

// ---------------- decoder GEMMs ----------------
template <bool ACT>
__global__ void __launch_bounds__(256) gemm_kernel(const float* __restrict__ A, const float* __restrict__ B,
                                                   const float* __restrict__ bias, float* __restrict__ C,
                                                   int M, int N, int K) {
    const int BK = 16;
    __shared__ float As[BK][68];
    __shared__ float Bs[BK][64];
    int tx = threadIdx.x & 15, ty = threadIdx.x >> 4;
    int bm = blockIdx.x * 64, bn = blockIdx.y * 64;
    float acc[4][4] = {};
    for (int k0 = 0; k0 < K; k0 += BK) {
        for (int idx = threadIdx.x; idx < 64 * BK; idx += 256) {
            int r = idx >> 4, kk = idx & 15;
            As[kk][r] = (k0 + kk < K) ? A[(size_t)(bm + r) * K + k0 + kk] : 0.f;
        }
        for (int idx = threadIdx.x; idx < BK * 64; idx += 256) {
            int kk = idx >> 6, cc = idx & 63;
            Bs[kk][cc] = (k0 + kk < K) ? B[(size_t)(k0 + kk) * N + bn + cc] : 0.f;
        }
        __syncthreads();
#pragma unroll
        for (int kk = 0; kk < BK; kk++) {
            float4 av = *(const float4*)&As[kk][ty * 4];
            float4 bv = *(const float4*)&Bs[kk][tx * 4];
            float a[4] = {av.x, av.y, av.z, av.w};
            float bb[4] = {bv.x, bv.y, bv.z, bv.w};
#pragma unroll
            for (int i = 0; i < 4; i++)
#pragma unroll
                for (int j = 0; j < 4; j++) acc[i][j] += a[i] * bb[j];
        }
        __syncthreads();
    }
#pragma unroll
    for (int i = 0; i < 4; i++) {
        int r = bm + ty * 4 + i;
#pragma unroll
        for (int j = 0; j < 4; j++) {
            int cc = bn + tx * 4 + j;
            float v = acc[i][j] + bias[cc];
            if (ACT) v -= tanhf(v);
            C[(size_t)r * N + cc] = v;
        }
    }
}

__global__ void __launch_bounds__(256) final_gemv(const float* __restrict__ H1, const float* __restrict__ w,
                                                  const float* __restrict__ b2, float* __restrict__ out) {
    int b = blockIdx.x * 8 + (threadIdx.x >> 5);
    int lane = threadIdx.x & 31;
    const float* row = H1 + (size_t)b * 256;
    float acc = 0.f;
#pragma unroll
    for (int k = lane; k < 256; k += 32) acc += row[k] * w[k];
#pragma unroll
    for (int o = 16; o; o >>= 1) acc += __shfl_down_sync(0xffffffffu, acc, o);
    if (lane == 0) out[b] = acc + b2[0];
}

// ---------------- launch ----------------
extern "C" void kernel_launch(void* const* d_in, const int* in_sizes, int n_in,
                              void* d_out, int out_size) {
    const float* in_t = (const float*)d_in[0];
    MainParams P;
    P.in = in_t;
    P.dists = (const float*)d_in[1];
    P.gamma = (const float*)d_in[3];  P.beta = (const float*)d_in[4];
    P.xe_w1 = (const float*)d_in[5];  P.xe_b1 = (const float*)d_in[6];
    P.xe_w2 = (const float*)d_in[7];  P.xe_b2 = (const float*)d_in[8];
    P.ye_w1 = (const float*)d_in[9];  P.ye_b1 = (const float*)d_in[10];
    P.ye_w2 = (const float*)d_in[11]; P.ye_b2 = (const float*)d_in[12];
    P.learnable_y = (const float*)d_in[13];
    P.hidden_tokens = (const float*)d_in[14];
    P.Wq = (const float*)d_in[15]; P.Wk = (const float*)d_in[16];
    P.Wv = (const float*)d_in[17]; P.Wo = (const float*)d_in[18];
    P.Wq2 = (const float*)d_in[19]; P.Wk2 = (const float*)d_in[20];
    P.Wv2 = (const float*)d_in[21]; P.Wo2 = (const float*)d_in[22];
    const float* dec_w0 = (const float*)d_in[23];
    const float* dec_b0 = (const float*)d_in[24];
    const float* dec_w1 = (const float*)d_in[25];
    const float* dec_b1 = (const float*)d_in[26];
    const float* dec_w2 = (const float*)d_in[27];
    const float* dec_b2 = (const float*)d_in[28];
    float* out = (float*)d_out;

    float *enc, *h0, *h1;
    cudaGetSymbolAddress((void**)&enc, g_enc);
    cudaGetSymbolAddress((void**)&h0, g_h0);
    cudaGetSymbolAddress((void**)&h1, g_h1);

    cudaFuncSetAttribute((const void*)k_main, cudaFuncAttributeMaxDynamicSharedMemorySize,
                         (int)sizeof(Smem));

    bn_zero_kernel<<<1, 32>>>();
    bn_acc_kernel<<<256, 256>>>(in_t);
    bn_fin_kernel<<<1, 32>>>();
    k_main<<<BSZ / 2, 256, sizeof(Smem)>>>(P, enc);
    gemm_kernel<true><<<dim3(BSZ / 64, 512 / 64), 256>>>(enc, dec_w0, dec_b0, h0, BSZ, 512, DEC_IN);
    gemm_kernel<true><<<dim3(BSZ / 64, 256 / 64), 256>>>(h0, dec_w1, dec_b1, h1, BSZ, 256, 512);
    final_gemv<<<BSZ / 8, 256>>>(h1, dec_w2, dec_b2, out);
}